// round 1
// baseline (speedup 1.0000x reference)
#include <cuda_runtime.h>

// Problem constants (fixed by the reference setup)
#define DIMC   1024
#define NHEAD  16
#define HDIM   64
#define BATCH  2
#define MAXT   2048
#define MAXM   (BATCH * MAXT)

// Scratch (no cudaMalloc allowed): QKV activations and attention output
__device__ float g_qkv[(size_t)MAXM * 3 * DIMC];   // [B*T, 3C]
__device__ float g_attn[(size_t)MAXM * DIMC];      // [B*T, C]

// ---------------------------------------------------------------------------
// Tiled fp32 GEMM + bias: C[M,N] = A[M,K] @ B[K,N] + bias[N]
// 64x64 block tile, 16 k-slice, 256 threads, 4x4 register microtile.
// ---------------------------------------------------------------------------
__global__ __launch_bounds__(256) void gemm_bias_kernel(
    const float* __restrict__ A, const float* __restrict__ B,
    const float* __restrict__ bias, float* __restrict__ C,
    int M, int N, int K)
{
    __shared__ float As[64][16];
    __shared__ float Bs[16][64];

    const int tid  = threadIdx.x;
    const int row0 = blockIdx.y * 64;
    const int col0 = blockIdx.x * 64;
    const int tx   = tid & 15;
    const int ty   = tid >> 4;

    // load mapping
    const int ar = tid >> 2;          // 0..63  (A tile row)
    const int ac = (tid & 3) * 4;     // 0,4,8,12 (A tile k-offset)
    const int br = tid >> 4;          // 0..15  (B tile k-row)
    const int bc = (tid & 15) * 4;    // 0..60  (B tile col)

    float acc[4][4];
    #pragma unroll
    for (int i = 0; i < 4; i++)
        #pragma unroll
        for (int j = 0; j < 4; j++) acc[i][j] = 0.f;

    for (int k0 = 0; k0 < K; k0 += 16) {
        float4 av = *reinterpret_cast<const float4*>(&A[(size_t)(row0 + ar) * K + k0 + ac]);
        *reinterpret_cast<float4*>(&As[ar][ac]) = av;
        float4 bv = *reinterpret_cast<const float4*>(&B[(size_t)(k0 + br) * N + col0 + bc]);
        *reinterpret_cast<float4*>(&Bs[br][bc]) = bv;
        __syncthreads();

        #pragma unroll
        for (int kk = 0; kk < 16; kk++) {
            float bm[4], am[4];
            float4 bq = *reinterpret_cast<const float4*>(&Bs[kk][tx * 4]);
            bm[0] = bq.x; bm[1] = bq.y; bm[2] = bq.z; bm[3] = bq.w;
            #pragma unroll
            for (int i = 0; i < 4; i++) am[i] = As[ty * 4 + i][kk];
            #pragma unroll
            for (int i = 0; i < 4; i++)
                #pragma unroll
                for (int j = 0; j < 4; j++)
                    acc[i][j] += am[i] * bm[j];
        }
        __syncthreads();
    }

    #pragma unroll
    for (int i = 0; i < 4; i++) {
        const int r = row0 + ty * 4 + i;
        #pragma unroll
        for (int j = 0; j < 4; j++) {
            const int c = col0 + tx * 4 + j;
            C[(size_t)r * N + c] = acc[i][j] + bias[c];
        }
    }
}

// ---------------------------------------------------------------------------
// Causal flash attention over g_qkv -> g_attn.
// Block: one (q-tile of 64, head, batch). 256 threads.
// Thread (row = tid>>2, sub = tid&3): owns q-row `row`; computes 16 score
// columns (sub*16..) and 16 output dims (sub*16..). Online softmax with
// cross-sub shfl reductions (groups of 4 consecutive lanes).
// ---------------------------------------------------------------------------
__global__ __launch_bounds__(256) void attn_kernel(int T)
{
    __shared__ float ks[64][64];
    __shared__ float vs[64][64];
    __shared__ float ps[64][64];   // staged Q first, then probabilities

    const int qt  = blockIdx.x;
    const int h   = blockIdx.y;
    const int b   = blockIdx.z;
    const int tid = threadIdx.x;
    const int row = tid >> 2;
    const int sub = tid & 3;
    const int q0  = qt * 64;
    const float scale = 0.125f;   // 1/sqrt(64)

    // Stage Q tile coalesced into ps, then lift own row into registers.
    for (int i = tid; i < 64 * 64; i += 256) {
        const int r = i >> 6, d = i & 63;
        ps[r][d] = g_qkv[(size_t)(b * T + q0 + r) * (3 * DIMC) + h * HDIM + d];
    }
    __syncthreads();
    float qreg[64];
    #pragma unroll
    for (int d = 0; d < 64; d++) qreg[d] = ps[row][d];

    float m_i = -1e30f, l_i = 0.f;
    float acc[16];
    #pragma unroll
    for (int i = 0; i < 16; i++) acc[i] = 0.f;

    for (int kt = 0; kt <= qt; kt++) {
        __syncthreads();   // ks/vs (and ps) safe to overwrite
        for (int i = tid; i < 64 * 64; i += 256) {
            const int r = i >> 6, d = i & 63;
            const size_t base = (size_t)(b * T + kt * 64 + r) * (3 * DIMC) + h * HDIM + d;
            ks[r][d] = g_qkv[base + DIMC];
            vs[r][d] = g_qkv[base + 2 * DIMC];
        }
        __syncthreads();

        // scores for this thread's 16 columns
        float s[16];
        float mloc = -1e30f;
        #pragma unroll
        for (int jj = 0; jj < 16; jj++) {
            const int j = sub * 16 + jj;
            float a = 0.f;
            #pragma unroll
            for (int d = 0; d < 64; d++) a += qreg[d] * ks[j][d];
            a *= scale;
            if (kt * 64 + j > q0 + row) a = -1e30f;   // causal mask (diag tile only)
            s[jj] = a;
            mloc = fmaxf(mloc, a);
        }
        mloc = fmaxf(mloc, __shfl_xor_sync(0xffffffffu, mloc, 1));
        mloc = fmaxf(mloc, __shfl_xor_sync(0xffffffffu, mloc, 2));

        const float m_new = fmaxf(m_i, mloc);
        const float corr  = __expf(m_i - m_new);
        float lsum = 0.f;
        #pragma unroll
        for (int jj = 0; jj < 16; jj++) {
            const float p = __expf(s[jj] - m_new);
            lsum += p;
            ps[row][sub * 16 + jj] = p;
        }
        lsum += __shfl_xor_sync(0xffffffffu, lsum, 1);
        lsum += __shfl_xor_sync(0xffffffffu, lsum, 2);
        l_i = l_i * corr + lsum;
        m_i = m_new;
        #pragma unroll
        for (int i = 0; i < 16; i++) acc[i] *= corr;

        __syncwarp();   // probs written/read within the same warp's 4-lane groups

        // PV: acc[dd] += sum_j p[row][j] * v[j][sub*16+dd]
        for (int j = 0; j < 64; j++) {
            const float p = ps[row][j];
            #pragma unroll
            for (int dd = 0; dd < 16; dd++)
                acc[dd] += p * vs[j][sub * 16 + dd];
        }
    }

    const float inv_l = 1.f / l_i;
    const int t = q0 + row;
    #pragma unroll
    for (int dd = 0; dd < 16; dd++)
        g_attn[(size_t)(b * T + t) * DIMC + h * HDIM + sub * 16 + dd] = acc[dd] * inv_l;
}

// ---------------------------------------------------------------------------
// Launch
// ---------------------------------------------------------------------------
extern "C" void kernel_launch(void* const* d_in, const int* in_sizes, int n_in,
                              void* d_out, int out_size)
{
    const float* x      = (const float*)d_in[0];   // [B,T,C]
    const float* W_qkv  = (const float*)d_in[1];   // [C, 3C]
    const float* b_qkv  = (const float*)d_in[2];   // [3C]
    const float* W_proj = (const float*)d_in[3];   // [C, C]
    const float* b_proj = (const float*)d_in[4];   // [C]
    float* out = (float*)d_out;

    const int M = in_sizes[0] / DIMC;   // B*T = 4096
    const int T = M / BATCH;            // 2048

    float* qkv_ptr  = nullptr;
    float* attn_ptr = nullptr;
    cudaGetSymbolAddress((void**)&qkv_ptr,  g_qkv);
    cudaGetSymbolAddress((void**)&attn_ptr, g_attn);

    // 1) QKV = x @ W_qkv + b_qkv          [M, 3072]
    {
        dim3 grid((3 * DIMC) / 64, M / 64);
        gemm_bias_kernel<<<grid, 256>>>(x, W_qkv, b_qkv, qkv_ptr, M, 3 * DIMC, DIMC);
    }

    // 2) causal attention -> g_attn       [M, 1024]
    {
        dim3 grid(T / 64, NHEAD, BATCH);
        attn_kernel<<<grid, 256>>>(T);
    }

    // 3) out = g_attn @ W_proj + b_proj   [M, 1024]
    {
        dim3 grid(DIMC / 64, M / 64);
        gemm_bias_kernel<<<grid, 256>>>(attn_ptr, W_proj, b_proj, out, M, DIMC, DIMC);
    }
}

// round 2
// speedup vs baseline: 8.5576x; 8.5576x over previous
#include <cuda_runtime.h>

#define DIMC   1024
#define NHEAD  16
#define HDIM   64
#define BATCH  2
#define MAXT   2048
#define MAXM   (BATCH * MAXT)

__device__ float g_qkv[(size_t)MAXM * 3 * DIMC];   // [B*T, 3C]
__device__ float g_attn[(size_t)MAXM * DIMC];      // [B*T, C]

// ---------------------------------------------------------------------------
// helpers
// ---------------------------------------------------------------------------
__device__ __forceinline__ float f2tf32(float x) {
    unsigned u;
    asm("cvt.rna.tf32.f32 %0, %1;" : "=r"(u) : "f"(x));
    return __uint_as_float(u);
}

__device__ __forceinline__ void mma_tf32(float* d, const unsigned* a, const unsigned* b) {
    asm volatile(
        "mma.sync.aligned.m16n8k8.row.col.f32.tf32.tf32.f32 "
        "{%0,%1,%2,%3}, {%4,%5,%6,%7}, {%8,%9}, {%0,%1,%2,%3};\n"
        : "+f"(d[0]), "+f"(d[1]), "+f"(d[2]), "+f"(d[3])
        : "r"(a[0]), "r"(a[1]), "r"(a[2]), "r"(a[3]), "r"(b[0]), "r"(b[1]));
}

// ---------------------------------------------------------------------------
// TF32 GEMM + bias: C[M,N] = A[M,K] @ B[K,N] + bias[N]
// 128x128 block tile, BK=32, 256 threads (8 warps), warp tile 32x64.
// ---------------------------------------------------------------------------
#define GLDA 36    // As leading dim (pad 4): frag-read banks == lane -> conflict free
#define GLDB 136   // Bs leading dim (pad 8): frag-read banks 8*(lane%4)+(lane>>2) -> conflict free

__global__ __launch_bounds__(256) void gemm_tf32_kernel(
    const float* __restrict__ A, const float* __restrict__ B,
    const float* __restrict__ bias, float* __restrict__ C,
    int M, int N, int K)
{
    __shared__ float As[128 * GLDA];
    __shared__ float Bs[32 * GLDB];

    const int tid  = threadIdx.x;
    const int lane = tid & 31;
    const int warp = tid >> 5;
    const int g    = lane >> 2;   // group id
    const int t    = lane & 3;    // thread in group

    const int wr = (warp >> 1) * 32;  // warp row base in tile
    const int wc = (warp & 1) * 64;   // warp col base in tile

    const int row0 = blockIdx.y * 128;
    const int col0 = blockIdx.x * 128;

    float acc[2][8][4];
    #pragma unroll
    for (int mt = 0; mt < 2; mt++)
        #pragma unroll
        for (int nt = 0; nt < 8; nt++)
            #pragma unroll
            for (int i = 0; i < 4; i++) acc[mt][nt][i] = 0.f;

    for (int k0 = 0; k0 < K; k0 += 32) {
        // stage A tile 128x32 (tf32-converted)
        #pragma unroll
        for (int it = 0; it < 4; it++) {
            int linear = it * 1024 + tid * 4;
            int r = linear >> 5, c = linear & 31;
            float4 v = *reinterpret_cast<const float4*>(&A[(size_t)(row0 + r) * K + k0 + c]);
            float* dst = &As[r * GLDA + c];
            dst[0] = f2tf32(v.x); dst[1] = f2tf32(v.y);
            dst[2] = f2tf32(v.z); dst[3] = f2tf32(v.w);
        }
        // stage B tile 32x128
        #pragma unroll
        for (int it = 0; it < 4; it++) {
            int linear = it * 1024 + tid * 4;
            int r = linear >> 7, c = linear & 127;
            float4 v = *reinterpret_cast<const float4*>(&B[(size_t)(k0 + r) * N + col0 + c]);
            float* dst = &Bs[r * GLDB + c];
            dst[0] = f2tf32(v.x); dst[1] = f2tf32(v.y);
            dst[2] = f2tf32(v.z); dst[3] = f2tf32(v.w);
        }
        __syncthreads();

        #pragma unroll
        for (int ks = 0; ks < 4; ks++) {
            const int k = ks * 8;
            unsigned af[2][4];
            #pragma unroll
            for (int mt = 0; mt < 2; mt++) {
                const int rb = wr + mt * 16 + g;
                af[mt][0] = __float_as_uint(As[(rb    ) * GLDA + k + t    ]);
                af[mt][1] = __float_as_uint(As[(rb + 8) * GLDA + k + t    ]);
                af[mt][2] = __float_as_uint(As[(rb    ) * GLDA + k + t + 4]);
                af[mt][3] = __float_as_uint(As[(rb + 8) * GLDA + k + t + 4]);
            }
            #pragma unroll
            for (int nt = 0; nt < 8; nt++) {
                unsigned bf[2];
                const int n = wc + nt * 8 + g;
                bf[0] = __float_as_uint(Bs[(k + t    ) * GLDB + n]);
                bf[1] = __float_as_uint(Bs[(k + t + 4) * GLDB + n]);
                mma_tf32(acc[0][nt], af[0], bf);
                mma_tf32(acc[1][nt], af[1], bf);
            }
        }
        __syncthreads();
    }

    // epilogue with bias
    #pragma unroll
    for (int mt = 0; mt < 2; mt++) {
        const int r0 = row0 + wr + mt * 16 + g;
        #pragma unroll
        for (int nt = 0; nt < 8; nt++) {
            const int c = col0 + wc + nt * 8 + 2 * t;
            const float b0 = bias[c], b1 = bias[c + 1];
            float2 v0 = make_float2(acc[mt][nt][0] + b0, acc[mt][nt][1] + b1);
            float2 v1 = make_float2(acc[mt][nt][2] + b0, acc[mt][nt][3] + b1);
            *reinterpret_cast<float2*>(&C[(size_t)r0 * N + c])       = v0;
            *reinterpret_cast<float2*>(&C[(size_t)(r0 + 8) * N + c]) = v1;
        }
    }
}

// ---------------------------------------------------------------------------
// Causal flash attention with TF32 tensor cores.
// Block = (q-tile of 128, head, batch). 256 threads, 8 warps.
// Each warp owns a 16-row strip of Q; scores live in mma accumulators;
// online softmax in registers (2 rows/thread); P staged through smem
// (warp-private rows, __syncwarp only); PV via second mma.
// ---------------------------------------------------------------------------
#define LDP 68   // Ps/Qs-staging leading dim: A-frag banks == lane -> conflict free
#define LDK 72   // Kt/Vs leading dim: B-frag banks 8*(lane%4)+(lane>>2) -> conflict free

__global__ __launch_bounds__(256) void attn_tf32_kernel(int T)
{
    extern __shared__ float sm[];
    float* Ps = sm;                       // 128 * LDP   (also Q staging)
    float* Kt = Ps + 128 * LDP;           // 64 * LDK    (K transposed: [d][kv])
    float* Vs = Kt + 64 * LDK;            // 64 * LDK    ([kv][d])

    const int qt  = blockIdx.x;
    const int h   = blockIdx.y;
    const int b   = blockIdx.z;
    const int tid = threadIdx.x;
    const int lane = tid & 31;
    const int warp = tid >> 5;
    const int g = lane >> 2;
    const int t = lane & 3;

    const int q0 = qt * 128;
    const int rb = warp * 16;            // warp's row base within q tile
    const size_t rowstride = 3 * DIMC;
    const float scale = 0.125f;          // 1/sqrt(64)

    // ---- stage Q tile into Ps, lift this warp's A-fragments into registers
    for (int i = 0; i < 32; i++) {
        int linear = i * 256 + tid;
        int r = linear >> 6, d = linear & 63;
        float qv = g_qkv[(size_t)(b * T + q0 + r) * rowstride + h * HDIM + d];
        Ps[r * LDP + d] = f2tf32(qv);
    }
    __syncthreads();

    unsigned qf[8][4];
    #pragma unroll
    for (int ks = 0; ks < 8; ks++) {
        const int k = ks * 8;
        qf[ks][0] = __float_as_uint(Ps[(rb + g    ) * LDP + k + t    ]);
        qf[ks][1] = __float_as_uint(Ps[(rb + g + 8) * LDP + k + t    ]);
        qf[ks][2] = __float_as_uint(Ps[(rb + g    ) * LDP + k + t + 4]);
        qf[ks][3] = __float_as_uint(Ps[(rb + g + 8) * LDP + k + t + 4]);
    }

    float o[8][4];
    #pragma unroll
    for (int nt = 0; nt < 8; nt++)
        #pragma unroll
        for (int i = 0; i < 4; i++) o[nt][i] = 0.f;

    float m0 = -1e30f, m1 = -1e30f, l0 = 0.f, l1 = 0.f;
    const int row0g = q0 + rb + g;       // global q index of this thread's row 0
    const int row1g = row0g + 8;

    const int nkv = 2 * qt + 2;
    for (int kt_i = 0; kt_i < nkv; kt_i++) {
        const int kv0 = kt_i * 64;
        __syncthreads();                 // prior tile's K/V reads complete
        // stage K (transposed) and V
        for (int i = 0; i < 16; i++) {
            int linear = i * 256 + tid;
            int kv = linear >> 6, d = linear & 63;
            size_t base = (size_t)(b * T + kv0 + kv) * rowstride + h * HDIM + d;
            Kt[d * LDK + kv] = f2tf32(g_qkv[base + DIMC]);
            Vs[kv * LDK + d] = f2tf32(g_qkv[base + 2 * DIMC]);
        }
        __syncthreads();

        // ---- S = Q @ K^T (per-warp 16x64 strip)
        float s[8][4];
        #pragma unroll
        for (int nt = 0; nt < 8; nt++)
            #pragma unroll
            for (int i = 0; i < 4; i++) s[nt][i] = 0.f;

        #pragma unroll
        for (int ks = 0; ks < 8; ks++) {
            const int k = ks * 8;
            #pragma unroll
            for (int nt = 0; nt < 8; nt++) {
                unsigned bf[2];
                const int n = nt * 8 + g;
                bf[0] = __float_as_uint(Kt[(k + t    ) * LDK + n]);
                bf[1] = __float_as_uint(Kt[(k + t + 4) * LDK + n]);
                mma_tf32(s[nt], qf[ks], bf);
            }
        }

        // ---- scale + causal mask + row max
        const bool do_mask = (kt_i >= 2 * qt);
        float m0loc = -1e30f, m1loc = -1e30f;
        #pragma unroll
        for (int nt = 0; nt < 8; nt++) {
            const int j = kv0 + nt * 8 + 2 * t;
            #pragma unroll
            for (int c = 0; c < 2; c++) {
                float v0 = s[nt][c] * scale;
                float v1 = s[nt][c + 2] * scale;
                if (do_mask) {
                    if (j + c > row0g) v0 = -1e30f;
                    if (j + c > row1g) v1 = -1e30f;
                }
                s[nt][c] = v0; s[nt][c + 2] = v1;
                m0loc = fmaxf(m0loc, v0);
                m1loc = fmaxf(m1loc, v1);
            }
        }
        m0loc = fmaxf(m0loc, __shfl_xor_sync(0xffffffffu, m0loc, 1));
        m0loc = fmaxf(m0loc, __shfl_xor_sync(0xffffffffu, m0loc, 2));
        m1loc = fmaxf(m1loc, __shfl_xor_sync(0xffffffffu, m1loc, 1));
        m1loc = fmaxf(m1loc, __shfl_xor_sync(0xffffffffu, m1loc, 2));

        const float m0n = fmaxf(m0, m0loc);
        const float m1n = fmaxf(m1, m1loc);
        const float corr0 = __expf(m0 - m0n);
        const float corr1 = __expf(m1 - m1n);

        float l0loc = 0.f, l1loc = 0.f;
        #pragma unroll
        for (int nt = 0; nt < 8; nt++) {
            const int col = nt * 8 + 2 * t;
            #pragma unroll
            for (int c = 0; c < 2; c++) {
                float p0 = __expf(s[nt][c]     - m0n);
                float p1 = __expf(s[nt][c + 2] - m1n);
                l0loc += p0; l1loc += p1;
                Ps[(rb + g    ) * LDP + col + c] = f2tf32(p0);
                Ps[(rb + g + 8) * LDP + col + c] = f2tf32(p1);
            }
        }
        l0loc += __shfl_xor_sync(0xffffffffu, l0loc, 1);
        l0loc += __shfl_xor_sync(0xffffffffu, l0loc, 2);
        l1loc += __shfl_xor_sync(0xffffffffu, l1loc, 1);
        l1loc += __shfl_xor_sync(0xffffffffu, l1loc, 2);

        l0 = l0 * corr0 + l0loc;
        l1 = l1 * corr1 + l1loc;
        m0 = m0n; m1 = m1n;

        #pragma unroll
        for (int nt = 0; nt < 8; nt++) {
            o[nt][0] *= corr0; o[nt][1] *= corr0;
            o[nt][2] *= corr1; o[nt][3] *= corr1;
        }
        __syncwarp();   // Ps rows are warp-private: warp sync suffices

        // ---- O += P @ V
        #pragma unroll
        for (int ks = 0; ks < 8; ks++) {
            const int k = ks * 8;
            unsigned pa[4];
            pa[0] = __float_as_uint(Ps[(rb + g    ) * LDP + k + t    ]);
            pa[1] = __float_as_uint(Ps[(rb + g + 8) * LDP + k + t    ]);
            pa[2] = __float_as_uint(Ps[(rb + g    ) * LDP + k + t + 4]);
            pa[3] = __float_as_uint(Ps[(rb + g + 8) * LDP + k + t + 4]);
            #pragma unroll
            for (int nt = 0; nt < 8; nt++) {
                unsigned vb[2];
                const int n = nt * 8 + g;
                vb[0] = __float_as_uint(Vs[(k + t    ) * LDK + n]);
                vb[1] = __float_as_uint(Vs[(k + t + 4) * LDK + n]);
                mma_tf32(o[nt], pa, vb);
            }
        }
        __syncwarp();   // Ps reads done before next tile overwrites
    }

    // ---- epilogue
    const float inv0 = 1.f / l0;
    const float inv1 = 1.f / l1;
    #pragma unroll
    for (int nt = 0; nt < 8; nt++) {
        const int d = nt * 8 + 2 * t;
        float2 v0 = make_float2(o[nt][0] * inv0, o[nt][1] * inv0);
        float2 v1 = make_float2(o[nt][2] * inv1, o[nt][3] * inv1);
        *reinterpret_cast<float2*>(&g_attn[(size_t)(b * T + row0g) * DIMC + h * HDIM + d]) = v0;
        *reinterpret_cast<float2*>(&g_attn[(size_t)(b * T + row1g) * DIMC + h * HDIM + d]) = v1;
    }
}

// ---------------------------------------------------------------------------
// Launch
// ---------------------------------------------------------------------------
extern "C" void kernel_launch(void* const* d_in, const int* in_sizes, int n_in,
                              void* d_out, int out_size)
{
    const float* x      = (const float*)d_in[0];
    const float* W_qkv  = (const float*)d_in[1];
    const float* b_qkv  = (const float*)d_in[2];
    const float* W_proj = (const float*)d_in[3];
    const float* b_proj = (const float*)d_in[4];
    float* out = (float*)d_out;

    const int M = in_sizes[0] / DIMC;   // 4096
    const int T = M / BATCH;            // 2048

    float* qkv_ptr  = nullptr;
    float* attn_ptr = nullptr;
    cudaGetSymbolAddress((void**)&qkv_ptr,  g_qkv);
    cudaGetSymbolAddress((void**)&attn_ptr, g_attn);

    const int attn_smem = (128 * LDP + 2 * 64 * LDK) * (int)sizeof(float);
    static bool attr_set = false;
    if (!attr_set) {
        cudaFuncSetAttribute(attn_tf32_kernel,
                             cudaFuncAttributeMaxDynamicSharedMemorySize, attn_smem);
        attr_set = true;
    }

    // 1) QKV = x @ W_qkv + b_qkv
    {
        dim3 grid((3 * DIMC) / 128, M / 128);
        gemm_tf32_kernel<<<grid, 256>>>(x, W_qkv, b_qkv, qkv_ptr, M, 3 * DIMC, DIMC);
    }
    // 2) causal attention
    {
        dim3 grid(T / 128, NHEAD, BATCH);
        attn_tf32_kernel<<<grid, 256, attn_smem>>>(T);
    }
    // 3) out = attn @ W_proj + b_proj
    {
        dim3 grid(DIMC / 128, M / 128);
        gemm_tf32_kernel<<<grid, 256>>>(attn_ptr, W_proj, b_proj, out, M, DIMC, DIMC);
    }
}

// round 4
// speedup vs baseline: 15.1802x; 1.7739x over previous
#include <cuda_runtime.h>
#include <cuda_fp16.h>
#include <cstdint>

#define DIMC   1024
#define NHEAD  16
#define HDIM   64
#define BATCH  2
#define MAXT   2048
#define MAXM   (BATCH * MAXT)

// Scratch (__device__ globals; no cudaMalloc allowed)
__device__ __half g_xh[(size_t)MAXM * DIMC];            // x fp16
__device__ __half g_wqkvT[(size_t)3 * DIMC * DIMC];     // W_qkv^T fp16 [3072][1024]
__device__ __half g_wprojT[(size_t)DIMC * DIMC];        // W_proj^T fp16 [1024][1024]
__device__ __half g_qkv[(size_t)MAXM * 3 * DIMC];       // QKV acts fp16 [B*T][3C]
__device__ __half g_vT[(size_t)BATCH * NHEAD * HDIM * MAXT]; // V^T fp16 [(b,h,d)][t]
__device__ __half g_attn[(size_t)MAXM * DIMC];          // attn out fp16 [B*T][C]

// ---------------------------------------------------------------------------
// helpers
// ---------------------------------------------------------------------------
__device__ __forceinline__ uint32_t smem_u32(const void* p) {
    uint32_t a;
    asm("{ .reg .u64 t; cvta.to.shared.u64 t, %1; cvt.u32.u64 %0, t; }" : "=r"(a) : "l"(p));
    return a;
}

#define CP_ASYNC16(dst_u32, src_ptr) \
    asm volatile("cp.async.cg.shared.global [%0], [%1], 16;" \
                 :: "r"(dst_u32), "l"(src_ptr) : "memory")
#define CP_COMMIT()  asm volatile("cp.async.commit_group;" ::: "memory")
#define CP_WAIT(n)   asm volatile("cp.async.wait_group %0;" :: "n"(n) : "memory")

__device__ __forceinline__ void mma_f16(float* d, const unsigned* a,
                                        unsigned b0, unsigned b1) {
    asm volatile(
        "mma.sync.aligned.m16n8k16.row.col.f32.f16.f16.f32 "
        "{%0,%1,%2,%3}, {%4,%5,%6,%7}, {%8,%9}, {%0,%1,%2,%3};\n"
        : "+f"(d[0]), "+f"(d[1]), "+f"(d[2]), "+f"(d[3])
        : "r"(a[0]), "r"(a[1]), "r"(a[2]), "r"(a[3]), "r"(b0), "r"(b1));
}

// ---------------------------------------------------------------------------
// Pre-pass kernels
// ---------------------------------------------------------------------------
__global__ __launch_bounds__(256) void conv_f16_kernel(const float* __restrict__ in,
                                                       __half* __restrict__ out, int n4) {
    int i = blockIdx.x * 256 + threadIdx.x;
    if (i < n4) {
        float4 v = reinterpret_cast<const float4*>(in)[i];
        __half2* o = reinterpret_cast<__half2*>(out + (size_t)i * 4);
        o[0] = __floats2half2_rn(v.x, v.y);
        o[1] = __floats2half2_rn(v.z, v.w);
    }
}

// out[n][k] = fp16(in[k][n]);  in: [K][N] fp32 row-major
__global__ __launch_bounds__(256) void transpose_f16_kernel(const float* __restrict__ in,
                                                            __half* __restrict__ out,
                                                            int K, int N) {
    __shared__ float t[32][33];
    const int k0 = blockIdx.y * 32, n0 = blockIdx.x * 32;
    const int tx = threadIdx.x, ty = threadIdx.y;   // (32, 8)
    #pragma unroll
    for (int i = 0; i < 4; i++)
        t[ty + 8 * i][tx] = in[(size_t)(k0 + ty + 8 * i) * N + n0 + tx];
    __syncthreads();
    #pragma unroll
    for (int i = 0; i < 4; i++)
        out[(size_t)(n0 + ty + 8 * i) * K + k0 + tx] = __float2half_rn(t[tx][ty + 8 * i]);
}

// g_vT[((b*H+h)*64+d)][t] = g_qkv[(b*T+t)][2C + h*64 + d]
__global__ __launch_bounds__(256) void vT_kernel(int T) {
    __shared__ __half t[32][33];
    const int bh = blockIdx.z;               // b*16 + h
    const int b = bh >> 4;
    const int t0 = blockIdx.x * 32, d0 = blockIdx.y * 32;
    const int tx = threadIdx.x, ty = threadIdx.y;   // (32, 8)
    const int hcol = 2 * DIMC + (bh & 15) * HDIM;
    #pragma unroll
    for (int i = 0; i < 4; i++)
        t[ty + 8 * i][tx] = g_qkv[(size_t)(b * T + t0 + ty + 8 * i) * (3 * DIMC) + hcol + d0 + tx];
    __syncthreads();
    #pragma unroll
    for (int i = 0; i < 4; i++)
        g_vT[(size_t)(bh * HDIM + d0 + ty + 8 * i) * T + t0 + tx] = t[tx][ty + 8 * i];
}

// ---------------------------------------------------------------------------
// fp16 GEMM + bias: C[M,N] = A[M,K](f16) @ Bt[N,K](f16)^T + bias(f32)
// 128x128 tile, BK=32, 256 threads (8 warps, warp tile 32x64),
// cp.async double-buffered, mma.sync.m16n8k16.
// ---------------------------------------------------------------------------
#define LDA 40   // halves; fragment reads conflict-free (20g+t pattern)
#define LDB 40

__global__ __launch_bounds__(256) void gemm_f16_kernel(
    const __half* __restrict__ A, const __half* __restrict__ Bt,
    const float* __restrict__ bias, void* __restrict__ Cout,
    int M, int N, int K, int half_out)
{
    __shared__ __half As[2][128 * LDA];
    __shared__ __half Bs[2][128 * LDB];

    const int tid  = threadIdx.x;
    const int lane = tid & 31;
    const int warp = tid >> 5;
    const int g = lane >> 2;
    const int t = lane & 3;
    const int wr = (warp >> 1) * 32;
    const int wc = (warp & 1) * 64;
    const int row0 = blockIdx.y * 128;
    const int col0 = blockIdx.x * 128;

    const uint32_t sA0 = smem_u32(&As[0][0]);
    const uint32_t sB0 = smem_u32(&Bs[0][0]);

    float acc[2][8][4];
    #pragma unroll
    for (int mt = 0; mt < 2; mt++)
        #pragma unroll
        for (int nt = 0; nt < 8; nt++)
            #pragma unroll
            for (int i = 0; i < 4; i++) acc[mt][nt][i] = 0.f;

    auto stage = [&](int ch, int buf) {
        const int k0 = ch * 32;
        const uint32_t sa = sA0 + buf * (128 * LDA * 2);
        const uint32_t sb = sB0 + buf * (128 * LDB * 2);
        #pragma unroll
        for (int it = 0; it < 2; it++) {
            const int idx = it * 256 + tid;        // 0..511
            const int r = idx >> 2, c = idx & 3;   // 128 rows x 4 x16B
            CP_ASYNC16(sa + (r * LDA + c * 8) * 2, A  + (size_t)(row0 + r) * K + k0 + c * 8);
            CP_ASYNC16(sb + (r * LDB + c * 8) * 2, Bt + (size_t)(col0 + r) * K + k0 + c * 8);
        }
    };

    auto compute = [&](int buf) {
        const __half* pA = &As[buf][0];
        const __half* pB = &Bs[buf][0];
        #pragma unroll
        for (int ks = 0; ks < 2; ks++) {
            const int k = ks * 16;
            unsigned af[2][4];
            #pragma unroll
            for (int mt = 0; mt < 2; mt++) {
                const int base = (wr + mt * 16 + g) * LDA + k + 2 * t;
                af[mt][0] = *reinterpret_cast<const unsigned*>(&pA[base]);
                af[mt][1] = *reinterpret_cast<const unsigned*>(&pA[base + 8 * LDA]);
                af[mt][2] = *reinterpret_cast<const unsigned*>(&pA[base + 8]);
                af[mt][3] = *reinterpret_cast<const unsigned*>(&pA[base + 8 * LDA + 8]);
            }
            #pragma unroll
            for (int nt = 0; nt < 8; nt++) {
                const int nb = (wc + nt * 8 + g) * LDB + k + 2 * t;
                unsigned b0 = *reinterpret_cast<const unsigned*>(&pB[nb]);
                unsigned b1 = *reinterpret_cast<const unsigned*>(&pB[nb + 8]);
                mma_f16(acc[0][nt], af[0], b0, b1);
                mma_f16(acc[1][nt], af[1], b0, b1);
            }
        }
    };

    const int NC = K / 32;
    stage(0, 0);
    CP_COMMIT();
    for (int i = 0; i < NC; i++) {
        if (i + 1 < NC) { stage(i + 1, (i + 1) & 1); CP_COMMIT(); CP_WAIT(1); }
        else            { CP_WAIT(0); }
        __syncthreads();
        compute(i & 1);
        __syncthreads();
    }

    // epilogue
    #pragma unroll
    for (int mt = 0; mt < 2; mt++) {
        const int r0 = row0 + wr + mt * 16 + g;
        #pragma unroll
        for (int nt = 0; nt < 8; nt++) {
            const int c = col0 + wc + nt * 8 + 2 * t;
            const float b0v = bias[c], b1v = bias[c + 1];
            if (half_out) {
                __half* Ch = (__half*)Cout;
                *reinterpret_cast<__half2*>(&Ch[(size_t)r0 * N + c]) =
                    __floats2half2_rn(acc[mt][nt][0] + b0v, acc[mt][nt][1] + b1v);
                *reinterpret_cast<__half2*>(&Ch[(size_t)(r0 + 8) * N + c]) =
                    __floats2half2_rn(acc[mt][nt][2] + b0v, acc[mt][nt][3] + b1v);
            } else {
                float* Cf = (float*)Cout;
                *reinterpret_cast<float2*>(&Cf[(size_t)r0 * N + c]) =
                    make_float2(acc[mt][nt][0] + b0v, acc[mt][nt][1] + b1v);
                *reinterpret_cast<float2*>(&Cf[(size_t)(r0 + 8) * N + c]) =
                    make_float2(acc[mt][nt][2] + b0v, acc[mt][nt][3] + b1v);
            }
        }
    }
}

// ---------------------------------------------------------------------------
// Causal flash attention, fp16 mma.sync. BQ=128, BKV=64, 256 threads.
// K tiles from g_qkv [kv][d]; V tiles from g_vT [d][kv] (both natural
// half2 B-fragments). cp.async double-buffered K/V staging.
// ---------------------------------------------------------------------------
#define LDS_ 72     // halves; frag banks 4g+t -> conflict free

__global__ __launch_bounds__(256) void attn_f16_kernel(int T)
{
    extern __shared__ __half sm[];
    __half* Ps = sm;                        // 128*LDS_ (Q staging, then P)
    __half* Ks = Ps + 128 * LDS_;           // 2 bufs x 64*LDS_
    __half* Vt = Ks + 2 * 64 * LDS_;        // 2 bufs x 64*LDS_
    const uint32_t sKs = smem_u32(Ks);
    const uint32_t sVt = smem_u32(Vt);

    const int qt  = blockIdx.x;
    const int h   = blockIdx.y;
    const int b   = blockIdx.z;
    const int tid = threadIdx.x;
    const int lane = tid & 31;
    const int warp = tid >> 5;
    const int g = lane >> 2;
    const int t = lane & 3;

    const int q0 = qt * 128;
    const int rb = warp * 16;
    const size_t rowstride = 3 * DIMC;
    const float scale = 0.125f;

    // ---- stage Q, lift A-fragments
    #pragma unroll
    for (int it = 0; it < 4; it++) {
        const int idx = it * 256 + tid;        // 128 rows x 8 x(8 halves)
        const int r = idx >> 3, c = idx & 7;
        *reinterpret_cast<uint4*>(&Ps[r * LDS_ + c * 8]) =
            *reinterpret_cast<const uint4*>(&g_qkv[(size_t)(b * T + q0 + r) * rowstride + h * HDIM + c * 8]);
    }
    __syncthreads();

    unsigned qf[4][4];
    #pragma unroll
    for (int ks = 0; ks < 4; ks++) {
        const int base = (rb + g) * LDS_ + ks * 16 + 2 * t;
        qf[ks][0] = *reinterpret_cast<const unsigned*>(&Ps[base]);
        qf[ks][1] = *reinterpret_cast<const unsigned*>(&Ps[base + 8 * LDS_]);
        qf[ks][2] = *reinterpret_cast<const unsigned*>(&Ps[base + 8]);
        qf[ks][3] = *reinterpret_cast<const unsigned*>(&Ps[base + 8 * LDS_ + 8]);
    }
    __syncthreads();   // everyone has Q frags before Ps is reused for P

    auto stageKV = [&](int kt_i, int buf) {
        const int kv0 = kt_i * 64;
        const uint32_t kb = sKs + buf * (64 * LDS_ * 2);
        const uint32_t vb = sVt + buf * (64 * LDS_ * 2);
        #pragma unroll
        for (int it = 0; it < 2; it++) {
            const int idx = it * 256 + tid;        // 64 rows x 8 chunks
            const int r = idx >> 3, c = idx & 7;
            CP_ASYNC16(kb + (r * LDS_ + c * 8) * 2,
                       &g_qkv[(size_t)(b * T + kv0 + r) * rowstride + DIMC + h * HDIM + c * 8]);
            CP_ASYNC16(vb + (r * LDS_ + c * 8) * 2,
                       &g_vT[(size_t)((b * NHEAD + h) * HDIM + r) * T + kv0 + c * 8]);
        }
    };

    float o[8][4];
    #pragma unroll
    for (int nt = 0; nt < 8; nt++)
        #pragma unroll
        for (int i = 0; i < 4; i++) o[nt][i] = 0.f;

    float m0 = -1e30f, m1 = -1e30f, l0 = 0.f, l1 = 0.f;
    const int row0g = q0 + rb + g;
    const int row1g = row0g + 8;

    const int nkv = 2 * qt + 2;
    stageKV(0, 0);
    CP_COMMIT();

    for (int kt_i = 0; kt_i < nkv; kt_i++) {
        if (kt_i + 1 < nkv) { stageKV(kt_i + 1, (kt_i + 1) & 1); CP_COMMIT(); CP_WAIT(1); }
        else                { CP_WAIT(0); }
        __syncthreads();

        const int buf = kt_i & 1;
        const __half* pK = Ks + buf * 64 * LDS_;
        const __half* pV = Vt + buf * 64 * LDS_;
        const int kv0 = kt_i * 64;

        // ---- S = Q @ K^T
        float s[8][4];
        #pragma unroll
        for (int nt = 0; nt < 8; nt++)
            #pragma unroll
            for (int i = 0; i < 4; i++) s[nt][i] = 0.f;

        #pragma unroll
        for (int ks = 0; ks < 4; ks++) {
            #pragma unroll
            for (int nt = 0; nt < 8; nt++) {
                const int nb = (nt * 8 + g) * LDS_ + ks * 16 + 2 * t;
                unsigned b0 = *reinterpret_cast<const unsigned*>(&pK[nb]);
                unsigned b1 = *reinterpret_cast<const unsigned*>(&pK[nb + 8]);
                mma_f16(s[nt], qf[ks], b0, b1);
            }
        }

        // ---- scale + mask + online softmax
        const bool do_mask = (kt_i >= 2 * qt);
        float m0loc = -1e30f, m1loc = -1e30f;
        #pragma unroll
        for (int nt = 0; nt < 8; nt++) {
            const int j = kv0 + nt * 8 + 2 * t;
            #pragma unroll
            for (int c = 0; c < 2; c++) {
                float v0 = s[nt][c] * scale;
                float v1 = s[nt][c + 2] * scale;
                if (do_mask) {
                    if (j + c > row0g) v0 = -1e30f;
                    if (j + c > row1g) v1 = -1e30f;
                }
                s[nt][c] = v0; s[nt][c + 2] = v1;
                m0loc = fmaxf(m0loc, v0);
                m1loc = fmaxf(m1loc, v1);
            }
        }
        m0loc = fmaxf(m0loc, __shfl_xor_sync(0xffffffffu, m0loc, 1));
        m0loc = fmaxf(m0loc, __shfl_xor_sync(0xffffffffu, m0loc, 2));
        m1loc = fmaxf(m1loc, __shfl_xor_sync(0xffffffffu, m1loc, 1));
        m1loc = fmaxf(m1loc, __shfl_xor_sync(0xffffffffu, m1loc, 2));

        const float m0n = fmaxf(m0, m0loc);
        const float m1n = fmaxf(m1, m1loc);
        const float corr0 = __expf(m0 - m0n);
        const float corr1 = __expf(m1 - m1n);

        float l0loc = 0.f, l1loc = 0.f;
        #pragma unroll
        for (int nt = 0; nt < 8; nt++) {
            const int col = nt * 8 + 2 * t;
            float p00 = __expf(s[nt][0] - m0n);
            float p01 = __expf(s[nt][1] - m0n);
            float p10 = __expf(s[nt][2] - m1n);
            float p11 = __expf(s[nt][3] - m1n);
            l0loc += p00 + p01;
            l1loc += p10 + p11;
            *reinterpret_cast<__half2*>(&Ps[(rb + g) * LDS_ + col])     = __floats2half2_rn(p00, p01);
            *reinterpret_cast<__half2*>(&Ps[(rb + g + 8) * LDS_ + col]) = __floats2half2_rn(p10, p11);
        }
        l0loc += __shfl_xor_sync(0xffffffffu, l0loc, 1);
        l0loc += __shfl_xor_sync(0xffffffffu, l0loc, 2);
        l1loc += __shfl_xor_sync(0xffffffffu, l1loc, 1);
        l1loc += __shfl_xor_sync(0xffffffffu, l1loc, 2);

        l0 = l0 * corr0 + l0loc;
        l1 = l1 * corr1 + l1loc;
        m0 = m0n; m1 = m1n;

        #pragma unroll
        for (int nt = 0; nt < 8; nt++) {
            o[nt][0] *= corr0; o[nt][1] *= corr0;
            o[nt][2] *= corr1; o[nt][3] *= corr1;
        }
        __syncwarp();   // Ps rows are warp-private

        // ---- O += P @ V
        #pragma unroll
        for (int ks = 0; ks < 4; ks++) {
            unsigned pa[4];
            const int base = (rb + g) * LDS_ + ks * 16 + 2 * t;
            pa[0] = *reinterpret_cast<const unsigned*>(&Ps[base]);
            pa[1] = *reinterpret_cast<const unsigned*>(&Ps[base + 8 * LDS_]);
            pa[2] = *reinterpret_cast<const unsigned*>(&Ps[base + 8]);
            pa[3] = *reinterpret_cast<const unsigned*>(&Ps[base + 8 * LDS_ + 8]);
            #pragma unroll
            for (int nt = 0; nt < 8; nt++) {
                const int nb = (nt * 8 + g) * LDS_ + ks * 16 + 2 * t;
                unsigned b0 = *reinterpret_cast<const unsigned*>(&pV[nb]);
                unsigned b1 = *reinterpret_cast<const unsigned*>(&pV[nb + 8]);
                mma_f16(o[nt], pa, b0, b1);
            }
        }
        __syncthreads();   // buf reads done before it is restaged
    }

    // ---- epilogue (fp16 out for proj GEMM)
    const float inv0 = 1.f / l0;
    const float inv1 = 1.f / l1;
    #pragma unroll
    for (int nt = 0; nt < 8; nt++) {
        const int d = nt * 8 + 2 * t;
        *reinterpret_cast<__half2*>(&g_attn[(size_t)(b * T + row0g) * DIMC + h * HDIM + d]) =
            __floats2half2_rn(o[nt][0] * inv0, o[nt][1] * inv0);
        *reinterpret_cast<__half2*>(&g_attn[(size_t)(b * T + row1g) * DIMC + h * HDIM + d]) =
            __floats2half2_rn(o[nt][2] * inv1, o[nt][3] * inv1);
    }
}

// ---------------------------------------------------------------------------
// Launch
// ---------------------------------------------------------------------------
extern "C" void kernel_launch(void* const* d_in, const int* in_sizes, int n_in,
                              void* d_out, int out_size)
{
    const float* x      = (const float*)d_in[0];
    const float* W_qkv  = (const float*)d_in[1];
    const float* b_qkv  = (const float*)d_in[2];
    const float* W_proj = (const float*)d_in[3];
    const float* b_proj = (const float*)d_in[4];
    float* out = (float*)d_out;

    const int M = in_sizes[0] / DIMC;   // 4096
    const int T = M / BATCH;            // 2048

    __half *xh, *wqkvT, *wprojT, *qkv, *attn;
    cudaGetSymbolAddress((void**)&xh,     g_xh);
    cudaGetSymbolAddress((void**)&wqkvT,  g_wqkvT);
    cudaGetSymbolAddress((void**)&wprojT, g_wprojT);
    cudaGetSymbolAddress((void**)&qkv,    g_qkv);
    cudaGetSymbolAddress((void**)&attn,   g_attn);

    const int attn_smem = (128 * LDS_ + 4 * 64 * LDS_) * (int)sizeof(__half);
    static bool attr_set = false;
    if (!attr_set) {
        cudaFuncSetAttribute(attn_f16_kernel,
                             cudaFuncAttributeMaxDynamicSharedMemorySize, attn_smem);
        attr_set = true;
    }

    // 0) pre-pass
    conv_f16_kernel<<<(M * DIMC / 4 + 255) / 256, 256>>>(x, xh, M * DIMC / 4);
    transpose_f16_kernel<<<dim3(3 * DIMC / 32, DIMC / 32), dim3(32, 8)>>>(W_qkv, wqkvT, DIMC, 3 * DIMC);
    transpose_f16_kernel<<<dim3(DIMC / 32, DIMC / 32), dim3(32, 8)>>>(W_proj, wprojT, DIMC, DIMC);

    // 1) QKV = x @ W_qkv + b_qkv   (fp16 out)
    gemm_f16_kernel<<<dim3(3 * DIMC / 128, M / 128), 256>>>(
        xh, wqkvT, b_qkv, qkv, M, 3 * DIMC, DIMC, 1);

    // 1b) V^T for attention PV fragments
    vT_kernel<<<dim3(T / 32, HDIM / 32, BATCH * NHEAD), dim3(32, 8)>>>(T);

    // 2) causal attention (fp16 out)
    attn_f16_kernel<<<dim3(T / 128, NHEAD, BATCH), 256, attn_smem>>>(T);

    // 3) out = attn @ W_proj + b_proj  (fp32 out)
    gemm_f16_kernel<<<dim3(DIMC / 128, M / 128), 256>>>(
        attn, wprojT, b_proj, out, M, DIMC, DIMC, 0);
}

// round 5
// speedup vs baseline: 16.1998x; 1.0672x over previous
#include <cuda_runtime.h>
#include <cuda_fp16.h>
#include <cstdint>

#define DIMC   1024
#define NHEAD  16
#define HDIM   64
#define BATCH  2
#define MAXT   2048
#define MAXM   (BATCH * MAXT)

// Scratch (__device__ globals; no cudaMalloc allowed)
__device__ __half g_xh[(size_t)MAXM * DIMC];
__device__ __half g_wqkvT[(size_t)3 * DIMC * DIMC];
__device__ __half g_wprojT[(size_t)DIMC * DIMC];
__device__ __half g_qkv[(size_t)MAXM * 3 * DIMC];
__device__ __half g_vT[(size_t)BATCH * NHEAD * HDIM * MAXT];
__device__ __half g_attn[(size_t)MAXM * DIMC];

// ---------------------------------------------------------------------------
// helpers
// ---------------------------------------------------------------------------
__device__ __forceinline__ uint32_t smem_u32(const void* p) {
    uint32_t a;
    asm("{ .reg .u64 t; cvta.to.shared.u64 t, %1; cvt.u32.u64 %0, t; }" : "=r"(a) : "l"(p));
    return a;
}

#define CP_ASYNC16(dst_u32, src_ptr) \
    asm volatile("cp.async.cg.shared.global [%0], [%1], 16;" \
                 :: "r"(dst_u32), "l"(src_ptr) : "memory")
#define CP_COMMIT()  asm volatile("cp.async.commit_group;" ::: "memory")
#define CP_WAIT(n)   asm volatile("cp.async.wait_group %0;" :: "n"(n) : "memory")

__device__ __forceinline__ void mma_f16(float* d, const unsigned* a,
                                        unsigned b0, unsigned b1) {
    asm volatile(
        "mma.sync.aligned.m16n8k16.row.col.f32.f16.f16.f32 "
        "{%0,%1,%2,%3}, {%4,%5,%6,%7}, {%8,%9}, {%0,%1,%2,%3};\n"
        : "+f"(d[0]), "+f"(d[1]), "+f"(d[2]), "+f"(d[3])
        : "r"(a[0]), "r"(a[1]), "r"(a[2]), "r"(a[3]), "r"(b0), "r"(b1));
}

__device__ __forceinline__ void ldmx4(unsigned* r, uint32_t addr) {
    asm volatile("ldmatrix.sync.aligned.m8n8.x4.shared.b16 {%0,%1,%2,%3}, [%4];"
                 : "=r"(r[0]), "=r"(r[1]), "=r"(r[2]), "=r"(r[3]) : "r"(addr));
}
__device__ __forceinline__ void ldmx2(unsigned& r0, unsigned& r1, uint32_t addr) {
    asm volatile("ldmatrix.sync.aligned.m8n8.x2.shared.b16 {%0,%1}, [%2];"
                 : "=r"(r0), "=r"(r1) : "r"(addr));
}

__device__ __forceinline__ unsigned pack2(float x, float y) {
    __half2 h = __floats2half2_rn(x, y);
    return *reinterpret_cast<unsigned*>(&h);
}

// ---------------------------------------------------------------------------
// Pre-pass kernels
// ---------------------------------------------------------------------------
__global__ __launch_bounds__(256) void conv_f16_kernel(const float* __restrict__ in,
                                                       __half* __restrict__ out, int n4) {
    int i = blockIdx.x * 256 + threadIdx.x;
    if (i < n4) {
        float4 v = reinterpret_cast<const float4*>(in)[i];
        __half2* o = reinterpret_cast<__half2*>(out + (size_t)i * 4);
        o[0] = __floats2half2_rn(v.x, v.y);
        o[1] = __floats2half2_rn(v.z, v.w);
    }
}

__global__ __launch_bounds__(256) void transpose_f16_kernel(const float* __restrict__ in,
                                                            __half* __restrict__ out,
                                                            int K, int N) {
    __shared__ float t[32][33];
    const int k0 = blockIdx.y * 32, n0 = blockIdx.x * 32;
    const int tx = threadIdx.x, ty = threadIdx.y;
    #pragma unroll
    for (int i = 0; i < 4; i++)
        t[ty + 8 * i][tx] = in[(size_t)(k0 + ty + 8 * i) * N + n0 + tx];
    __syncthreads();
    #pragma unroll
    for (int i = 0; i < 4; i++)
        out[(size_t)(n0 + ty + 8 * i) * K + k0 + tx] = __float2half_rn(t[tx][ty + 8 * i]);
}

__global__ __launch_bounds__(256) void vT_kernel(int T) {
    __shared__ __half t[32][33];
    const int bh = blockIdx.z;
    const int b = bh >> 4;
    const int t0 = blockIdx.x * 32, d0 = blockIdx.y * 32;
    const int tx = threadIdx.x, ty = threadIdx.y;
    const int hcol = 2 * DIMC + (bh & 15) * HDIM;
    #pragma unroll
    for (int i = 0; i < 4; i++)
        t[ty + 8 * i][tx] = g_qkv[(size_t)(b * T + t0 + ty + 8 * i) * (3 * DIMC) + hcol + d0 + tx];
    __syncthreads();
    #pragma unroll
    for (int i = 0; i < 4; i++)
        g_vT[(size_t)(bh * HDIM + d0 + ty + 8 * i) * T + t0 + tx] = t[tx][ty + 8 * i];
}

// ---------------------------------------------------------------------------
// fp16 GEMM + bias, ldmatrix + 3-stage cp.async pipeline.
// C[M,N] = A[M,K](f16) @ Bt[N,K](f16)^T + bias(f32)
// 128x128 tile, BK=32, 8 warps (warp tile 32x64).
// ---------------------------------------------------------------------------
#define LDA 40
#define G_STAGE  (2 * 128 * LDA * 2)        // bytes per stage (A + B)
#define G_BOFF   (128 * LDA * 2)            // B offset within stage
#define G_SMEM   (3 * G_STAGE)              // 61440 bytes

__global__ __launch_bounds__(256) void gemm_f16_kernel(
    const __half* __restrict__ A, const __half* __restrict__ Bt,
    const float* __restrict__ bias, void* __restrict__ Cout,
    int M, int N, int K, int half_out)
{
    extern __shared__ char smraw[];
    const uint32_t s0 = smem_u32(smraw);

    const int tid  = threadIdx.x;
    const int lane = tid & 31;
    const int warp = tid >> 5;
    const int wr = (warp >> 1) * 32;
    const int wc = (warp & 1) * 64;
    const int row0 = blockIdx.y * 128;
    const int col0 = blockIdx.x * 128;

    float acc[2][8][4];
    #pragma unroll
    for (int mt = 0; mt < 2; mt++)
        #pragma unroll
        for (int nt = 0; nt < 8; nt++)
            #pragma unroll
            for (int i = 0; i < 4; i++) acc[mt][nt][i] = 0.f;

    auto stage = [&](int ch, int buf) {
        const int k0 = ch * 32;
        const uint32_t base = s0 + buf * G_STAGE;
        #pragma unroll
        for (int it = 0; it < 2; it++) {
            const int idx = it * 256 + tid;        // 512: 128 rows x 4 chunks
            const int r = idx >> 2, c = idx & 3;
            CP_ASYNC16(base + (r * LDA + c * 8) * 2,
                       A + (size_t)(row0 + r) * K + k0 + c * 8);
            CP_ASYNC16(base + G_BOFF + (r * LDA + c * 8) * 2,
                       Bt + (size_t)(col0 + r) * K + k0 + c * 8);
        }
    };

    // per-lane ldmatrix address components
    const int a_row = lane & 15, a_koff = (lane >> 4) << 3;
    const int b_row = lane & 7,  b_koff = (lane >> 3) << 3;   // 0,8,16,24

    auto compute = [&](int buf) {
        const uint32_t base = s0 + buf * G_STAGE;
        unsigned af[2][2][4];
        #pragma unroll
        for (int ks = 0; ks < 2; ks++)
            #pragma unroll
            for (int mt = 0; mt < 2; mt++)
                ldmx4(af[ks][mt],
                      base + ((wr + mt * 16 + a_row) * LDA + ks * 16 + a_koff) * 2);
        #pragma unroll
        for (int nt = 0; nt < 8; nt++) {
            unsigned b[4];
            ldmx4(b, base + G_BOFF + ((wc + nt * 8 + b_row) * LDA + b_koff) * 2);
            mma_f16(acc[0][nt], af[0][0], b[0], b[1]);
            mma_f16(acc[1][nt], af[0][1], b[0], b[1]);
            mma_f16(acc[0][nt], af[1][0], b[2], b[3]);
            mma_f16(acc[1][nt], af[1][1], b[2], b[3]);
        }
    };

    const int NC = K / 32;
    stage(0, 0); CP_COMMIT();
    stage(1, 1); CP_COMMIT();
    for (int i = 0; i < NC; i++) {
        CP_WAIT(1);
        __syncthreads();
        if (i + 2 < NC) stage(i + 2, (i + 2) % 3);
        CP_COMMIT();
        compute(i % 3);
    }

    const int g = lane >> 2, t = lane & 3;
    #pragma unroll
    for (int mt = 0; mt < 2; mt++) {
        const int r0 = row0 + wr + mt * 16 + g;
        #pragma unroll
        for (int nt = 0; nt < 8; nt++) {
            const int c = col0 + wc + nt * 8 + 2 * t;
            const float b0v = bias[c], b1v = bias[c + 1];
            if (half_out) {
                __half* Ch = (__half*)Cout;
                *reinterpret_cast<__half2*>(&Ch[(size_t)r0 * N + c]) =
                    __floats2half2_rn(acc[mt][nt][0] + b0v, acc[mt][nt][1] + b1v);
                *reinterpret_cast<__half2*>(&Ch[(size_t)(r0 + 8) * N + c]) =
                    __floats2half2_rn(acc[mt][nt][2] + b0v, acc[mt][nt][3] + b1v);
            } else {
                float* Cf = (float*)Cout;
                *reinterpret_cast<float2*>(&Cf[(size_t)r0 * N + c]) =
                    make_float2(acc[mt][nt][0] + b0v, acc[mt][nt][1] + b1v);
                *reinterpret_cast<float2*>(&Cf[(size_t)(r0 + 8) * N + c]) =
                    make_float2(acc[mt][nt][2] + b0v, acc[mt][nt][3] + b1v);
            }
        }
    }
}

// ---------------------------------------------------------------------------
// Causal flash attention: ldmatrix K/V frags, P kept in registers
// (S-accumulator layout == A-fragment layout), 3-stage cp.async KV pipeline.
// BQ=128, BKV=64, 256 threads (8 warps x 16 q-rows).
// ---------------------------------------------------------------------------
#define LDS_ 72
#define AT_QBYTES   (128 * LDS_ * 2)
#define AT_KVSTAGE  (2 * 64 * LDS_ * 2)     // K + V per stage
#define AT_VOFF     (64 * LDS_ * 2)
#define AT_SMEM     (AT_QBYTES + 3 * AT_KVSTAGE)   // 73728 bytes

__global__ __launch_bounds__(256) void attn_f16_kernel(int T)
{
    extern __shared__ char smraw[];
    const uint32_t sQ  = smem_u32(smraw);
    const uint32_t sKV = sQ + AT_QBYTES;

    const int qt  = gridDim.x - 1 - blockIdx.x;   // heavy tiles first
    const int h   = blockIdx.y;
    const int b   = blockIdx.z;
    const int tid = threadIdx.x;
    const int lane = tid & 31;
    const int warp = tid >> 5;
    const int g = lane >> 2;
    const int t = lane & 3;

    const int q0 = qt * 128;
    const int rb = warp * 16;
    const size_t rowstride = 3 * DIMC;
    const float scale = 0.125f;

    // ---- stage Q tile, extract A-fragments via ldmatrix
    __half* Qs = (__half*)smraw;
    #pragma unroll
    for (int it = 0; it < 4; it++) {
        const int idx = it * 256 + tid;
        const int r = idx >> 3, c = idx & 7;
        *reinterpret_cast<uint4*>(&Qs[r * LDS_ + c * 8]) =
            *reinterpret_cast<const uint4*>(
                &g_qkv[(size_t)(b * T + q0 + r) * rowstride + h * HDIM + c * 8]);
    }
    __syncthreads();

    const int a_row = lane & 15, a_koff = (lane >> 4) << 3;
    const int b_row = lane & 7,  b_koff = ((lane >> 3) & 1) << 3;

    unsigned qf[4][4];
    #pragma unroll
    for (int ks = 0; ks < 4; ks++)
        ldmx4(qf[ks], sQ + ((rb + a_row) * LDS_ + ks * 16 + a_koff) * 2);

    auto stageKV = [&](int kt_i, int buf) {
        const int kv0 = kt_i * 64;
        const uint32_t base = sKV + buf * AT_KVSTAGE;
        #pragma unroll
        for (int it = 0; it < 2; it++) {
            const int idx = it * 256 + tid;        // 512: 64 rows x 8 chunks
            const int r = idx >> 3, c = idx & 7;
            CP_ASYNC16(base + (r * LDS_ + c * 8) * 2,
                       &g_qkv[(size_t)(b * T + kv0 + r) * rowstride + DIMC + h * HDIM + c * 8]);
            CP_ASYNC16(base + AT_VOFF + (r * LDS_ + c * 8) * 2,
                       &g_vT[(size_t)((b * NHEAD + h) * HDIM + r) * T + kv0 + c * 8]);
        }
    };

    float o[8][4];
    #pragma unroll
    for (int nt = 0; nt < 8; nt++)
        #pragma unroll
        for (int i = 0; i < 4; i++) o[nt][i] = 0.f;

    float m0 = -1e30f, m1 = -1e30f, l0 = 0.f, l1 = 0.f;
    const int row0g = q0 + rb + g;
    const int row1g = row0g + 8;

    const int nkv = 2 * qt + 2;
    stageKV(0, 0); CP_COMMIT();
    if (nkv > 1) stageKV(1, 1);
    CP_COMMIT();

    for (int kt_i = 0; kt_i < nkv; kt_i++) {
        CP_WAIT(1);
        __syncthreads();
        if (kt_i + 2 < nkv) stageKV(kt_i + 2, (kt_i + 2) % 3);
        CP_COMMIT();

        const uint32_t kb = sKV + (kt_i % 3) * AT_KVSTAGE;
        const uint32_t vb = kb + AT_VOFF;
        const int kv0 = kt_i * 64;

        // ---- S = Q @ K^T
        float s[8][4];
        #pragma unroll
        for (int nt = 0; nt < 8; nt++)
            #pragma unroll
            for (int i = 0; i < 4; i++) s[nt][i] = 0.f;

        #pragma unroll
        for (int ks = 0; ks < 4; ks++) {
            #pragma unroll
            for (int nt = 0; nt < 8; nt++) {
                unsigned k0r, k1r;
                ldmx2(k0r, k1r, kb + ((nt * 8 + b_row) * LDS_ + ks * 16 + b_koff) * 2);
                mma_f16(s[nt], qf[ks], k0r, k1r);
            }
        }

        // ---- scale + causal mask + online softmax (registers only)
        const bool do_mask = (kt_i >= 2 * qt);
        float m0loc = -1e30f, m1loc = -1e30f;
        #pragma unroll
        for (int nt = 0; nt < 8; nt++) {
            const int j = kv0 + nt * 8 + 2 * t;
            #pragma unroll
            for (int c = 0; c < 2; c++) {
                float v0 = s[nt][c] * scale;
                float v1 = s[nt][c + 2] * scale;
                if (do_mask) {
                    if (j + c > row0g) v0 = -1e30f;
                    if (j + c > row1g) v1 = -1e30f;
                }
                s[nt][c] = v0; s[nt][c + 2] = v1;
                m0loc = fmaxf(m0loc, v0);
                m1loc = fmaxf(m1loc, v1);
            }
        }
        m0loc = fmaxf(m0loc, __shfl_xor_sync(0xffffffffu, m0loc, 1));
        m0loc = fmaxf(m0loc, __shfl_xor_sync(0xffffffffu, m0loc, 2));
        m1loc = fmaxf(m1loc, __shfl_xor_sync(0xffffffffu, m1loc, 1));
        m1loc = fmaxf(m1loc, __shfl_xor_sync(0xffffffffu, m1loc, 2));

        const float m0n = fmaxf(m0, m0loc);
        const float m1n = fmaxf(m1, m1loc);
        const float corr0 = __expf(m0 - m0n);
        const float corr1 = __expf(m1 - m1n);

        float l0loc = 0.f, l1loc = 0.f;
        #pragma unroll
        for (int nt = 0; nt < 8; nt++) {
            float p00 = __expf(s[nt][0] - m0n);
            float p01 = __expf(s[nt][1] - m0n);
            float p10 = __expf(s[nt][2] - m1n);
            float p11 = __expf(s[nt][3] - m1n);
            l0loc += p00 + p01;
            l1loc += p10 + p11;
            s[nt][0] = p00; s[nt][1] = p01; s[nt][2] = p10; s[nt][3] = p11;
        }
        l0loc += __shfl_xor_sync(0xffffffffu, l0loc, 1);
        l0loc += __shfl_xor_sync(0xffffffffu, l0loc, 2);
        l1loc += __shfl_xor_sync(0xffffffffu, l1loc, 1);
        l1loc += __shfl_xor_sync(0xffffffffu, l1loc, 2);

        l0 = l0 * corr0 + l0loc;
        l1 = l1 * corr1 + l1loc;
        m0 = m0n; m1 = m1n;

        #pragma unroll
        for (int nt = 0; nt < 8; nt++) {
            o[nt][0] *= corr0; o[nt][1] *= corr0;
            o[nt][2] *= corr1; o[nt][3] *= corr1;
        }

        // ---- O += P @ V  (P fragments built directly from registers)
        #pragma unroll
        for (int ks = 0; ks < 4; ks++) {
            unsigned pa[4];
            pa[0] = pack2(s[2 * ks][0],     s[2 * ks][1]);
            pa[1] = pack2(s[2 * ks][2],     s[2 * ks][3]);
            pa[2] = pack2(s[2 * ks + 1][0], s[2 * ks + 1][1]);
            pa[3] = pack2(s[2 * ks + 1][2], s[2 * ks + 1][3]);
            #pragma unroll
            for (int nt = 0; nt < 8; nt++) {
                unsigned v0r, v1r;
                ldmx2(v0r, v1r, vb + ((nt * 8 + b_row) * LDS_ + ks * 16 + b_koff) * 2);
                mma_f16(o[nt], pa, v0r, v1r);
            }
        }
    }

    // ---- epilogue (fp16 out for proj GEMM)
    const float inv0 = 1.f / l0;
    const float inv1 = 1.f / l1;
    #pragma unroll
    for (int nt = 0; nt < 8; nt++) {
        const int d = nt * 8 + 2 * t;
        *reinterpret_cast<__half2*>(&g_attn[(size_t)(b * T + row0g) * DIMC + h * HDIM + d]) =
            __floats2half2_rn(o[nt][0] * inv0, o[nt][1] * inv0);
        *reinterpret_cast<__half2*>(&g_attn[(size_t)(b * T + row1g) * DIMC + h * HDIM + d]) =
            __floats2half2_rn(o[nt][2] * inv1, o[nt][3] * inv1);
    }
}

// ---------------------------------------------------------------------------
// Launch
// ---------------------------------------------------------------------------
extern "C" void kernel_launch(void* const* d_in, const int* in_sizes, int n_in,
                              void* d_out, int out_size)
{
    const float* x      = (const float*)d_in[0];
    const float* W_qkv  = (const float*)d_in[1];
    const float* b_qkv  = (const float*)d_in[2];
    const float* W_proj = (const float*)d_in[3];
    const float* b_proj = (const float*)d_in[4];
    float* out = (float*)d_out;

    const int M = in_sizes[0] / DIMC;   // 4096
    const int T = M / BATCH;            // 2048

    __half *xh, *wqkvT, *wprojT, *qkv, *attn;
    cudaGetSymbolAddress((void**)&xh,     g_xh);
    cudaGetSymbolAddress((void**)&wqkvT,  g_wqkvT);
    cudaGetSymbolAddress((void**)&wprojT, g_wprojT);
    cudaGetSymbolAddress((void**)&qkv,    g_qkv);
    cudaGetSymbolAddress((void**)&attn,   g_attn);

    static bool attr_set = false;
    if (!attr_set) {
        cudaFuncSetAttribute(gemm_f16_kernel,
                             cudaFuncAttributeMaxDynamicSharedMemorySize, G_SMEM);
        cudaFuncSetAttribute(attn_f16_kernel,
                             cudaFuncAttributeMaxDynamicSharedMemorySize, AT_SMEM);
        attr_set = true;
    }

    // 0) pre-pass
    conv_f16_kernel<<<(M * DIMC / 4 + 255) / 256, 256>>>(x, xh, M * DIMC / 4);
    transpose_f16_kernel<<<dim3(3 * DIMC / 32, DIMC / 32), dim3(32, 8)>>>(W_qkv, wqkvT, DIMC, 3 * DIMC);
    transpose_f16_kernel<<<dim3(DIMC / 32, DIMC / 32), dim3(32, 8)>>>(W_proj, wprojT, DIMC, DIMC);

    // 1) QKV = x @ W_qkv + b_qkv   (fp16 out)
    gemm_f16_kernel<<<dim3(3 * DIMC / 128, M / 128), 256, G_SMEM>>>(
        xh, wqkvT, b_qkv, qkv, M, 3 * DIMC, DIMC, 1);

    // 1b) V^T
    vT_kernel<<<dim3(T / 32, HDIM / 32, BATCH * NHEAD), dim3(32, 8)>>>(T);

    // 2) causal attention (fp16 out)
    attn_f16_kernel<<<dim3(T / 128, NHEAD, BATCH), 256, AT_SMEM>>>(T);

    // 3) out = attn @ W_proj + b_proj  (fp32 out)
    gemm_f16_kernel<<<dim3(DIMC / 128, M / 128), 256, G_SMEM>>>(
        attn, wprojT, b_proj, out, M, DIMC, DIMC, 0);
}

// round 6
// speedup vs baseline: 16.4132x; 1.0132x over previous
#include <cuda_runtime.h>
#include <cuda_fp16.h>
#include <cstdint>

#define DIMC   1024
#define NHEAD  16
#define HDIM   64
#define BATCH  2
#define MAXT   2048
#define MAXM   (BATCH * MAXT)

// Scratch (__device__ globals; no cudaMalloc allowed)
__device__ __half g_xh[(size_t)MAXM * DIMC];
__device__ __half g_wqkvT[(size_t)3 * DIMC * DIMC];
__device__ __half g_wprojT[(size_t)DIMC * DIMC];
__device__ __half g_qkv[(size_t)MAXM * 3 * DIMC];
__device__ __half g_vT[(size_t)BATCH * NHEAD * HDIM * MAXT];
__device__ __half g_attn[(size_t)MAXM * DIMC];

// ---------------------------------------------------------------------------
// helpers
// ---------------------------------------------------------------------------
__device__ __forceinline__ uint32_t smem_u32(const void* p) {
    uint32_t a;
    asm("{ .reg .u64 t; cvta.to.shared.u64 t, %1; cvt.u32.u64 %0, t; }" : "=r"(a) : "l"(p));
    return a;
}

#define CP_ASYNC16(dst_u32, src_ptr) \
    asm volatile("cp.async.cg.shared.global [%0], [%1], 16;" \
                 :: "r"(dst_u32), "l"(src_ptr) : "memory")
#define CP_COMMIT()  asm volatile("cp.async.commit_group;" ::: "memory")
#define CP_WAIT(n)   asm volatile("cp.async.wait_group %0;" :: "n"(n) : "memory")

__device__ __forceinline__ void mma_f16(float* d, const unsigned* a,
                                        unsigned b0, unsigned b1) {
    asm volatile(
        "mma.sync.aligned.m16n8k16.row.col.f32.f16.f16.f32 "
        "{%0,%1,%2,%3}, {%4,%5,%6,%7}, {%8,%9}, {%0,%1,%2,%3};\n"
        : "+f"(d[0]), "+f"(d[1]), "+f"(d[2]), "+f"(d[3])
        : "r"(a[0]), "r"(a[1]), "r"(a[2]), "r"(a[3]), "r"(b0), "r"(b1));
}

__device__ __forceinline__ void ldmx4(unsigned* r, uint32_t addr) {
    asm volatile("ldmatrix.sync.aligned.m8n8.x4.shared.b16 {%0,%1,%2,%3}, [%4];"
                 : "=r"(r[0]), "=r"(r[1]), "=r"(r[2]), "=r"(r[3]) : "r"(addr));
}

__device__ __forceinline__ unsigned pack2(float x, float y) {
    __half2 h = __floats2half2_rn(x, y);
    return *reinterpret_cast<unsigned*>(&h);
}

// ---------------------------------------------------------------------------
// Pre-pass kernels
// ---------------------------------------------------------------------------
__global__ __launch_bounds__(256) void conv_f16_kernel(const float* __restrict__ in,
                                                       __half* __restrict__ out, int n4) {
    int i = blockIdx.x * 256 + threadIdx.x;
    if (i < n4) {
        float4 v = reinterpret_cast<const float4*>(in)[i];
        __half2* o = reinterpret_cast<__half2*>(out + (size_t)i * 4);
        o[0] = __floats2half2_rn(v.x, v.y);
        o[1] = __floats2half2_rn(v.z, v.w);
    }
}

__global__ __launch_bounds__(256) void transpose_f16_kernel(const float* __restrict__ in,
                                                            __half* __restrict__ out,
                                                            int K, int N) {
    __shared__ float t[32][33];
    const int k0 = blockIdx.y * 32, n0 = blockIdx.x * 32;
    const int tx = threadIdx.x, ty = threadIdx.y;
    #pragma unroll
    for (int i = 0; i < 4; i++)
        t[ty + 8 * i][tx] = in[(size_t)(k0 + ty + 8 * i) * N + n0 + tx];
    __syncthreads();
    #pragma unroll
    for (int i = 0; i < 4; i++)
        out[(size_t)(n0 + ty + 8 * i) * K + k0 + tx] = __float2half_rn(t[tx][ty + 8 * i]);
}

__global__ __launch_bounds__(256) void vT_kernel(int T) {
    __shared__ __half t[32][33];
    const int bh = blockIdx.z;
    const int b = bh >> 4;
    const int t0 = blockIdx.x * 32, d0 = blockIdx.y * 32;
    const int tx = threadIdx.x, ty = threadIdx.y;
    const int hcol = 2 * DIMC + (bh & 15) * HDIM;
    #pragma unroll
    for (int i = 0; i < 4; i++)
        t[ty + 8 * i][tx] = g_qkv[(size_t)(b * T + t0 + ty + 8 * i) * (3 * DIMC) + hcol + d0 + tx];
    __syncthreads();
    #pragma unroll
    for (int i = 0; i < 4; i++)
        g_vT[(size_t)(bh * HDIM + d0 + ty + 8 * i) * T + t0 + tx] = t[tx][ty + 8 * i];
}

// ---------------------------------------------------------------------------
// fp16 GEMM + bias: 128x128 CTA tile, 4 warps (64x64 warp tile), BK=32,
// 3-stage cp.async pipeline, ldmatrix.x4 fragments.
// C[M,N] = A[M,K](f16) @ Bt[N,K](f16)^T + bias(f32)
// ---------------------------------------------------------------------------
#define LDA 40
#define G_STAGE  (2 * 128 * LDA * 2)
#define G_BOFF   (128 * LDA * 2)
#define G_SMEM   (3 * G_STAGE)              // 61440 bytes

__global__ __launch_bounds__(128) void gemm_f16_kernel(
    const __half* __restrict__ A, const __half* __restrict__ Bt,
    const float* __restrict__ bias, void* __restrict__ Cout,
    int M, int N, int K, int half_out)
{
    extern __shared__ char smraw[];
    const uint32_t s0 = smem_u32(smraw);

    const int tid  = threadIdx.x;
    const int lane = tid & 31;
    const int warp = tid >> 5;
    const int wr = (warp >> 1) * 64;
    const int wc = (warp & 1) * 64;
    const int row0 = blockIdx.y * 128;
    const int col0 = blockIdx.x * 128;

    float acc[4][8][4];
    #pragma unroll
    for (int mt = 0; mt < 4; mt++)
        #pragma unroll
        for (int nt = 0; nt < 8; nt++)
            #pragma unroll
            for (int i = 0; i < 4; i++) acc[mt][nt][i] = 0.f;

    auto stage = [&](int ch, int buf) {
        const int k0 = ch * 32;
        const uint32_t base = s0 + buf * G_STAGE;
        #pragma unroll
        for (int it = 0; it < 4; it++) {
            const int idx = it * 128 + tid;        // 512: 128 rows x 4 chunks
            const int r = idx >> 2, c = idx & 3;
            CP_ASYNC16(base + (r * LDA + c * 8) * 2,
                       A + (size_t)(row0 + r) * K + k0 + c * 8);
            CP_ASYNC16(base + G_BOFF + (r * LDA + c * 8) * 2,
                       Bt + (size_t)(col0 + r) * K + k0 + c * 8);
        }
    };

    const int f_row = lane & 15, f_k = (lane >> 4) << 3;

    auto compute = [&](int buf) {
        const uint32_t base = s0 + buf * G_STAGE;
        #pragma unroll
        for (int ks = 0; ks < 2; ks++) {
            unsigned af[4][4], bf[4][4];
            #pragma unroll
            for (int mt = 0; mt < 4; mt++)
                ldmx4(af[mt], base + ((wr + mt * 16 + f_row) * LDA + ks * 16 + f_k) * 2);
            #pragma unroll
            for (int ntp = 0; ntp < 4; ntp++)
                ldmx4(bf[ntp], base + G_BOFF + ((wc + ntp * 16 + f_row) * LDA + ks * 16 + f_k) * 2);
            #pragma unroll
            for (int mt = 0; mt < 4; mt++)
                #pragma unroll
                for (int ntp = 0; ntp < 4; ntp++) {
                    mma_f16(acc[mt][2 * ntp],     af[mt], bf[ntp][0], bf[ntp][2]);
                    mma_f16(acc[mt][2 * ntp + 1], af[mt], bf[ntp][1], bf[ntp][3]);
                }
        }
    };

    const int NC = K / 32;
    stage(0, 0); CP_COMMIT();
    stage(1, 1); CP_COMMIT();
    for (int i = 0; i < NC; i++) {
        CP_WAIT(1);
        __syncthreads();
        if (i + 2 < NC) stage(i + 2, (i + 2) % 3);
        CP_COMMIT();
        compute(i % 3);
    }

    const int g = lane >> 2, t = lane & 3;
    #pragma unroll
    for (int mt = 0; mt < 4; mt++) {
        const int r0 = row0 + wr + mt * 16 + g;
        #pragma unroll
        for (int nt = 0; nt < 8; nt++) {
            const int c = col0 + wc + nt * 8 + 2 * t;
            const float b0v = bias[c], b1v = bias[c + 1];
            if (half_out) {
                __half* Ch = (__half*)Cout;
                *reinterpret_cast<__half2*>(&Ch[(size_t)r0 * N + c]) =
                    __floats2half2_rn(acc[mt][nt][0] + b0v, acc[mt][nt][1] + b1v);
                *reinterpret_cast<__half2*>(&Ch[(size_t)(r0 + 8) * N + c]) =
                    __floats2half2_rn(acc[mt][nt][2] + b0v, acc[mt][nt][3] + b1v);
            } else {
                float* Cf = (float*)Cout;
                *reinterpret_cast<float2*>(&Cf[(size_t)r0 * N + c]) =
                    make_float2(acc[mt][nt][0] + b0v, acc[mt][nt][1] + b1v);
                *reinterpret_cast<float2*>(&Cf[(size_t)(r0 + 8) * N + c]) =
                    make_float2(acc[mt][nt][2] + b0v, acc[mt][nt][3] + b1v);
            }
        }
    }
}

// ---------------------------------------------------------------------------
// Causal flash attention: 4 warps (32x64 warp tile, 2 m16 tiles/warp),
// ldmatrix.x4 K/V fragments, P register-resident, 3-stage cp.async pipeline.
// BQ=128, BKV=64, 128 threads.
// ---------------------------------------------------------------------------
#define LDS_ 72
#define AT_QBYTES   (128 * LDS_ * 2)
#define AT_KVSTAGE  (2 * 64 * LDS_ * 2)
#define AT_VOFF     (64 * LDS_ * 2)
#define AT_SMEM     (AT_QBYTES + 3 * AT_KVSTAGE)   // 73728 bytes

__global__ __launch_bounds__(128) void attn_f16_kernel(int T)
{
    extern __shared__ char smraw[];
    const uint32_t sQ  = smem_u32(smraw);
    const uint32_t sKV = sQ + AT_QBYTES;

    const int qt  = gridDim.x - 1 - blockIdx.x;   // heavy tiles first
    const int h   = blockIdx.y;
    const int b   = blockIdx.z;
    const int tid = threadIdx.x;
    const int lane = tid & 31;
    const int warp = tid >> 5;
    const int g = lane >> 2;
    const int t = lane & 3;

    const int q0 = qt * 128;
    const int rb = warp * 32;
    const size_t rowstride = 3 * DIMC;
    const float scale = 0.125f;

    // ---- stage Q tile
    __half* Qs = (__half*)smraw;
    #pragma unroll
    for (int it = 0; it < 8; it++) {
        const int idx = it * 128 + tid;        // 1024: 128 rows x 8 chunks
        const int r = idx >> 3, c = idx & 7;
        *reinterpret_cast<uint4*>(&Qs[r * LDS_ + c * 8]) =
            *reinterpret_cast<const uint4*>(
                &g_qkv[(size_t)(b * T + q0 + r) * rowstride + h * HDIM + c * 8]);
    }
    __syncthreads();

    const int f_row = lane & 15, f_k = (lane >> 4) << 3;

    unsigned qf[4][2][4];   // [ks][mt]
    #pragma unroll
    for (int ks = 0; ks < 4; ks++)
        #pragma unroll
        for (int mt = 0; mt < 2; mt++)
            ldmx4(qf[ks][mt], sQ + ((rb + mt * 16 + f_row) * LDS_ + ks * 16 + f_k) * 2);

    auto stageKV = [&](int kt_i, int buf) {
        const int kv0 = kt_i * 64;
        const uint32_t base = sKV + buf * AT_KVSTAGE;
        #pragma unroll
        for (int it = 0; it < 4; it++) {
            const int idx = it * 128 + tid;        // 512: 64 rows x 8 chunks
            const int r = idx >> 3, c = idx & 7;
            CP_ASYNC16(base + (r * LDS_ + c * 8) * 2,
                       &g_qkv[(size_t)(b * T + kv0 + r) * rowstride + DIMC + h * HDIM + c * 8]);
            CP_ASYNC16(base + AT_VOFF + (r * LDS_ + c * 8) * 2,
                       &g_vT[(size_t)((b * NHEAD + h) * HDIM + r) * T + kv0 + c * 8]);
        }
    };

    float o[2][8][4];
    #pragma unroll
    for (int mt = 0; mt < 2; mt++)
        #pragma unroll
        for (int nt = 0; nt < 8; nt++)
            #pragma unroll
            for (int i = 0; i < 4; i++) o[mt][nt][i] = 0.f;

    float mx[2][2], ls[2][2];
    #pragma unroll
    for (int mt = 0; mt < 2; mt++) { mx[mt][0] = mx[mt][1] = -1e30f; ls[mt][0] = ls[mt][1] = 0.f; }

    const int nkv = 2 * qt + 2;
    stageKV(0, 0); CP_COMMIT();
    if (nkv > 1) stageKV(1, 1);
    CP_COMMIT();

    for (int kt_i = 0; kt_i < nkv; kt_i++) {
        CP_WAIT(1);
        __syncthreads();
        if (kt_i + 2 < nkv) stageKV(kt_i + 2, (kt_i + 2) % 3);
        CP_COMMIT();

        const uint32_t kb = sKV + (kt_i % 3) * AT_KVSTAGE;
        const uint32_t vb = kb + AT_VOFF;
        const int kv0 = kt_i * 64;

        // ---- S = Q @ K^T
        float s[2][8][4];
        #pragma unroll
        for (int mt = 0; mt < 2; mt++)
            #pragma unroll
            for (int nt = 0; nt < 8; nt++)
                #pragma unroll
                for (int i = 0; i < 4; i++) s[mt][nt][i] = 0.f;

        #pragma unroll
        for (int ks = 0; ks < 4; ks++) {
            #pragma unroll
            for (int ntp = 0; ntp < 4; ntp++) {
                unsigned kf[4];
                ldmx4(kf, kb + ((ntp * 16 + f_row) * LDS_ + ks * 16 + f_k) * 2);
                #pragma unroll
                for (int mt = 0; mt < 2; mt++) {
                    mma_f16(s[mt][2 * ntp],     qf[ks][mt], kf[0], kf[2]);
                    mma_f16(s[mt][2 * ntp + 1], qf[ks][mt], kf[1], kf[3]);
                }
            }
        }

        // ---- scale + causal mask + online softmax (registers only)
        const bool do_mask = (kt_i >= 2 * qt);
        #pragma unroll
        for (int mt = 0; mt < 2; mt++) {
            const int rg0 = q0 + rb + mt * 16 + g;
            const int rg1 = rg0 + 8;
            float m0loc = -1e30f, m1loc = -1e30f;
            #pragma unroll
            for (int nt = 0; nt < 8; nt++) {
                const int j = kv0 + nt * 8 + 2 * t;
                #pragma unroll
                for (int c = 0; c < 2; c++) {
                    float v0 = s[mt][nt][c] * scale;
                    float v1 = s[mt][nt][c + 2] * scale;
                    if (do_mask) {
                        if (j + c > rg0) v0 = -1e30f;
                        if (j + c > rg1) v1 = -1e30f;
                    }
                    s[mt][nt][c] = v0; s[mt][nt][c + 2] = v1;
                    m0loc = fmaxf(m0loc, v0);
                    m1loc = fmaxf(m1loc, v1);
                }
            }
            m0loc = fmaxf(m0loc, __shfl_xor_sync(0xffffffffu, m0loc, 1));
            m0loc = fmaxf(m0loc, __shfl_xor_sync(0xffffffffu, m0loc, 2));
            m1loc = fmaxf(m1loc, __shfl_xor_sync(0xffffffffu, m1loc, 1));
            m1loc = fmaxf(m1loc, __shfl_xor_sync(0xffffffffu, m1loc, 2));

            const float m0n = fmaxf(mx[mt][0], m0loc);
            const float m1n = fmaxf(mx[mt][1], m1loc);
            const float corr0 = __expf(mx[mt][0] - m0n);
            const float corr1 = __expf(mx[mt][1] - m1n);

            float l0loc = 0.f, l1loc = 0.f;
            #pragma unroll
            for (int nt = 0; nt < 8; nt++) {
                float p00 = __expf(s[mt][nt][0] - m0n);
                float p01 = __expf(s[mt][nt][1] - m0n);
                float p10 = __expf(s[mt][nt][2] - m1n);
                float p11 = __expf(s[mt][nt][3] - m1n);
                l0loc += p00 + p01;
                l1loc += p10 + p11;
                s[mt][nt][0] = p00; s[mt][nt][1] = p01;
                s[mt][nt][2] = p10; s[mt][nt][3] = p11;
            }
            l0loc += __shfl_xor_sync(0xffffffffu, l0loc, 1);
            l0loc += __shfl_xor_sync(0xffffffffu, l0loc, 2);
            l1loc += __shfl_xor_sync(0xffffffffu, l1loc, 1);
            l1loc += __shfl_xor_sync(0xffffffffu, l1loc, 2);

            ls[mt][0] = ls[mt][0] * corr0 + l0loc;
            ls[mt][1] = ls[mt][1] * corr1 + l1loc;
            mx[mt][0] = m0n; mx[mt][1] = m1n;

            #pragma unroll
            for (int nt = 0; nt < 8; nt++) {
                o[mt][nt][0] *= corr0; o[mt][nt][1] *= corr0;
                o[mt][nt][2] *= corr1; o[mt][nt][3] *= corr1;
            }
        }

        // ---- O += P @ V  (P fragments from registers; V^T B-frags via ldmx4)
        #pragma unroll
        for (int ks = 0; ks < 4; ks++) {
            unsigned pa[2][4];
            #pragma unroll
            for (int mt = 0; mt < 2; mt++) {
                pa[mt][0] = pack2(s[mt][2 * ks][0],     s[mt][2 * ks][1]);
                pa[mt][1] = pack2(s[mt][2 * ks][2],     s[mt][2 * ks][3]);
                pa[mt][2] = pack2(s[mt][2 * ks + 1][0], s[mt][2 * ks + 1][1]);
                pa[mt][3] = pack2(s[mt][2 * ks + 1][2], s[mt][2 * ks + 1][3]);
            }
            #pragma unroll
            for (int ntp = 0; ntp < 4; ntp++) {
                unsigned vf[4];
                ldmx4(vf, vb + ((ntp * 16 + f_row) * LDS_ + ks * 16 + f_k) * 2);
                #pragma unroll
                for (int mt = 0; mt < 2; mt++) {
                    mma_f16(o[mt][2 * ntp],     pa[mt], vf[0], vf[2]);
                    mma_f16(o[mt][2 * ntp + 1], pa[mt], vf[1], vf[3]);
                }
            }
        }
    }

    // ---- epilogue (fp16 out for proj GEMM)
    #pragma unroll
    for (int mt = 0; mt < 2; mt++) {
        const float inv0 = 1.f / ls[mt][0];
        const float inv1 = 1.f / ls[mt][1];
        const int rg0 = q0 + rb + mt * 16 + g;
        #pragma unroll
        for (int nt = 0; nt < 8; nt++) {
            const int d = nt * 8 + 2 * t;
            *reinterpret_cast<__half2*>(&g_attn[(size_t)(b * T + rg0) * DIMC + h * HDIM + d]) =
                __floats2half2_rn(o[mt][nt][0] * inv0, o[mt][nt][1] * inv0);
            *reinterpret_cast<__half2*>(&g_attn[(size_t)(b * T + rg0 + 8) * DIMC + h * HDIM + d]) =
                __floats2half2_rn(o[mt][nt][2] * inv1, o[mt][nt][3] * inv1);
        }
    }
}

// ---------------------------------------------------------------------------
// Launch
// ---------------------------------------------------------------------------
extern "C" void kernel_launch(void* const* d_in, const int* in_sizes, int n_in,
                              void* d_out, int out_size)
{
    const float* x      = (const float*)d_in[0];
    const float* W_qkv  = (const float*)d_in[1];
    const float* b_qkv  = (const float*)d_in[2];
    const float* W_proj = (const float*)d_in[3];
    const float* b_proj = (const float*)d_in[4];
    float* out = (float*)d_out;

    const int M = in_sizes[0] / DIMC;   // 4096
    const int T = M / BATCH;            // 2048

    __half *xh, *wqkvT, *wprojT, *qkv, *attn;
    cudaGetSymbolAddress((void**)&xh,     g_xh);
    cudaGetSymbolAddress((void**)&wqkvT,  g_wqkvT);
    cudaGetSymbolAddress((void**)&wprojT, g_wprojT);
    cudaGetSymbolAddress((void**)&qkv,    g_qkv);
    cudaGetSymbolAddress((void**)&attn,   g_attn);

    static bool attr_set = false;
    if (!attr_set) {
        cudaFuncSetAttribute(gemm_f16_kernel,
                             cudaFuncAttributeMaxDynamicSharedMemorySize, G_SMEM);
        cudaFuncSetAttribute(attn_f16_kernel,
                             cudaFuncAttributeMaxDynamicSharedMemorySize, AT_SMEM);
        attr_set = true;
    }

    // 0) pre-pass
    conv_f16_kernel<<<(M * DIMC / 4 + 255) / 256, 256>>>(x, xh, M * DIMC / 4);
    transpose_f16_kernel<<<dim3(3 * DIMC / 32, DIMC / 32), dim3(32, 8)>>>(W_qkv, wqkvT, DIMC, 3 * DIMC);
    transpose_f16_kernel<<<dim3(DIMC / 32, DIMC / 32), dim3(32, 8)>>>(W_proj, wprojT, DIMC, DIMC);

    // 1) QKV = x @ W_qkv + b_qkv   (fp16 out)
    gemm_f16_kernel<<<dim3(3 * DIMC / 128, M / 128), 128, G_SMEM>>>(
        xh, wqkvT, b_qkv, qkv, M, 3 * DIMC, DIMC, 1);

    // 1b) V^T
    vT_kernel<<<dim3(T / 32, HDIM / 32, BATCH * NHEAD), dim3(32, 8)>>>(T);

    // 2) causal attention (fp16 out)
    attn_f16_kernel<<<dim3(T / 128, NHEAD, BATCH), 128, AT_SMEM>>>(T);

    // 3) out = attn @ W_proj + b_proj  (fp32 out)
    gemm_f16_kernel<<<dim3(DIMC / 128, M / 128), 128, G_SMEM>>>(
        attn, wprojT, b_proj, out, M, DIMC, DIMC, 0);
}

// round 7
// speedup vs baseline: 17.6139x; 1.0732x over previous
#include <cuda_runtime.h>
#include <cuda_fp16.h>
#include <cstdint>

#define DIMC   1024
#define NHEAD  16
#define HDIM   64
#define BATCH  2
#define MAXT   2048
#define MAXM   (BATCH * MAXT)

// q scale folded into Q at QKV epilogue: 1/sqrt(64) * log2(e)
#define QSCALE (0.125f * 1.4426950408889634f)

// Scratch (__device__ globals; no cudaMalloc allowed)
__device__ __half g_xh[(size_t)MAXM * DIMC];
__device__ __half g_wqkvT[(size_t)3 * DIMC * DIMC];
__device__ __half g_wprojT[(size_t)DIMC * DIMC];
__device__ __half g_qkv[(size_t)MAXM * 3 * DIMC];
__device__ __half g_attn[(size_t)MAXM * DIMC];

// ---------------------------------------------------------------------------
// helpers
// ---------------------------------------------------------------------------
__device__ __forceinline__ uint32_t smem_u32(const void* p) {
    uint32_t a;
    asm("{ .reg .u64 t; cvta.to.shared.u64 t, %1; cvt.u32.u64 %0, t; }" : "=r"(a) : "l"(p));
    return a;
}

#define CP_ASYNC16(dst_u32, src_ptr) \
    asm volatile("cp.async.cg.shared.global [%0], [%1], 16;" \
                 :: "r"(dst_u32), "l"(src_ptr) : "memory")
#define CP_COMMIT()  asm volatile("cp.async.commit_group;" ::: "memory")
#define CP_WAIT(n)   asm volatile("cp.async.wait_group %0;" :: "n"(n) : "memory")

__device__ __forceinline__ void mma_f16(float* d, const unsigned* a,
                                        unsigned b0, unsigned b1) {
    asm volatile(
        "mma.sync.aligned.m16n8k16.row.col.f32.f16.f16.f32 "
        "{%0,%1,%2,%3}, {%4,%5,%6,%7}, {%8,%9}, {%0,%1,%2,%3};\n"
        : "+f"(d[0]), "+f"(d[1]), "+f"(d[2]), "+f"(d[3])
        : "r"(a[0]), "r"(a[1]), "r"(a[2]), "r"(a[3]), "r"(b0), "r"(b1));
}

__device__ __forceinline__ void ldmx4(unsigned* r, uint32_t addr) {
    asm volatile("ldmatrix.sync.aligned.m8n8.x4.shared.b16 {%0,%1,%2,%3}, [%4];"
                 : "=r"(r[0]), "=r"(r[1]), "=r"(r[2]), "=r"(r[3]) : "r"(addr));
}
__device__ __forceinline__ void ldmx4t(unsigned* r, uint32_t addr) {
    asm volatile("ldmatrix.sync.aligned.m8n8.x4.trans.shared.b16 {%0,%1,%2,%3}, [%4];"
                 : "=r"(r[0]), "=r"(r[1]), "=r"(r[2]), "=r"(r[3]) : "r"(addr));
}

__device__ __forceinline__ unsigned pack2(float x, float y) {
    __half2 h = __floats2half2_rn(x, y);
    return *reinterpret_cast<unsigned*>(&h);
}
__device__ __forceinline__ float ex2f(float x) {
    float y;
    asm("ex2.approx.f32 %0, %1;" : "=f"(y) : "f"(x));
    return y;
}

// ---------------------------------------------------------------------------
// Pre-pass kernels
// ---------------------------------------------------------------------------
__global__ __launch_bounds__(256) void conv_f16_kernel(const float* __restrict__ in,
                                                       __half* __restrict__ out, int n4) {
    int i = blockIdx.x * 256 + threadIdx.x;
    if (i < n4) {
        float4 v = reinterpret_cast<const float4*>(in)[i];
        __half2* o = reinterpret_cast<__half2*>(out + (size_t)i * 4);
        o[0] = __floats2half2_rn(v.x, v.y);
        o[1] = __floats2half2_rn(v.z, v.w);
    }
}

__global__ __launch_bounds__(256) void transpose_f16_kernel(const float* __restrict__ in,
                                                            __half* __restrict__ out,
                                                            int K, int N) {
    __shared__ float t[32][33];
    const int k0 = blockIdx.y * 32, n0 = blockIdx.x * 32;
    const int tx = threadIdx.x, ty = threadIdx.y;
    #pragma unroll
    for (int i = 0; i < 4; i++)
        t[ty + 8 * i][tx] = in[(size_t)(k0 + ty + 8 * i) * N + n0 + tx];
    __syncthreads();
    #pragma unroll
    for (int i = 0; i < 4; i++)
        out[(size_t)(n0 + ty + 8 * i) * K + k0 + tx] = __float2half_rn(t[tx][ty + 8 * i]);
}

// ---------------------------------------------------------------------------
// fp16 GEMM + bias: 128(M) x 256(N) CTA tile, 8 warps (64x64 warp tiles),
// BK=32, 3-stage cp.async pipeline with register-rotated buffer bases.
// C[M,N] = A[M,K] @ Bt[N,K]^T + bias.  Columns < q_cols get *QSCALE (fp16 out).
// ---------------------------------------------------------------------------
#define LDA   40
#define G_ASZ (128 * LDA * 2)          // 10240 B
#define G_BSZ (256 * LDA * 2)          // 20480 B
#define G_STAGE (G_ASZ + G_BSZ)        // 30720 B
#define G_SMEM  (3 * G_STAGE)          // 92160 B

__global__ __launch_bounds__(256, 1) void gemm_f16_kernel(
    const __half* __restrict__ A, const __half* __restrict__ Bt,
    const float* __restrict__ bias, void* __restrict__ Cout,
    int M, int N, int K, int half_out, int q_cols)
{
    extern __shared__ char smraw[];
    const uint32_t s0 = smem_u32(smraw);

    const int tid  = threadIdx.x;
    const int lane = tid & 31;
    const int warp = tid >> 5;
    const int wr = (warp >> 2) * 64;     // 0 / 64
    const int wc = (warp & 3) * 64;      // 0..192
    const int row0 = blockIdx.y * 128;
    const int col0 = blockIdx.x * 256;

    float acc[4][8][4];
    #pragma unroll
    for (int mt = 0; mt < 4; mt++)
        #pragma unroll
        for (int nt = 0; nt < 8; nt++)
            #pragma unroll
            for (int i = 0; i < 4; i++) acc[mt][nt][i] = 0.f;

    // hoisted staging addresses
    const __half* pA = A  + (size_t)(row0 + (tid >> 2)) * K + (tid & 3) * 8;
    const __half* pB = Bt + (size_t)(col0 + (tid >> 2)) * K + (tid & 3) * 8;
    const uint32_t dA = ((tid >> 2) * LDA + (tid & 3) * 8) * 2;
    const uint32_t dB = dA;

    auto stage = [&](int k0, uint32_t base) {
        #pragma unroll
        for (int it = 0; it < 2; it++)
            CP_ASYNC16(base + dA + it * (64 * LDA * 2),
                       pA + k0 + (size_t)it * 64 * K);
        #pragma unroll
        for (int it = 0; it < 4; it++)
            CP_ASYNC16(base + G_ASZ + dB + it * (64 * LDA * 2),
                       pB + k0 + (size_t)it * 64 * K);
    };

    const int f_row = lane & 15, f_k = (lane >> 4) << 3;
    const uint32_t aoff = (f_row * LDA + f_k) * 2 + wr * (LDA * 2);
    const uint32_t boff = G_ASZ + (f_row * LDA + f_k) * 2 + wc * (LDA * 2);

    auto compute = [&](uint32_t base) {
        #pragma unroll
        for (int ks = 0; ks < 2; ks++) {
            unsigned af[4][4], bf[4][4];
            #pragma unroll
            for (int mt = 0; mt < 4; mt++)
                ldmx4(af[mt], base + aoff + ks * 32 + mt * (16 * LDA * 2));
            #pragma unroll
            for (int ntp = 0; ntp < 4; ntp++)
                ldmx4(bf[ntp], base + boff + ks * 32 + ntp * (16 * LDA * 2));
            #pragma unroll
            for (int mt = 0; mt < 4; mt++)
                #pragma unroll
                for (int ntp = 0; ntp < 4; ntp++) {
                    mma_f16(acc[mt][2 * ntp],     af[mt], bf[ntp][0], bf[ntp][2]);
                    mma_f16(acc[mt][2 * ntp + 1], af[mt], bf[ntp][1], bf[ntp][3]);
                }
        }
    };

    uint32_t cb0 = s0, cb1 = s0 + G_STAGE, cb2 = s0 + 2 * G_STAGE;

    const int NC = K / 32;
    stage(0,  cb0); CP_COMMIT();
    stage(32, cb1); CP_COMMIT();
    for (int i = 0; i < NC; i++) {
        CP_WAIT(1);
        __syncthreads();
        if (i + 2 < NC) stage((i + 2) * 32, cb2);
        CP_COMMIT();
        compute(cb0);
        uint32_t t0 = cb0; cb0 = cb1; cb1 = cb2; cb2 = t0;
    }

    const int g = lane >> 2, t = lane & 3;
    #pragma unroll
    for (int mt = 0; mt < 4; mt++) {
        const int r0 = row0 + wr + mt * 16 + g;
        #pragma unroll
        for (int nt = 0; nt < 8; nt++) {
            const int c = col0 + wc + nt * 8 + 2 * t;
            const float qs = (c < q_cols) ? QSCALE : 1.f;
            const float b0v = bias[c], b1v = bias[c + 1];
            if (half_out) {
                __half* Ch = (__half*)Cout;
                *reinterpret_cast<__half2*>(&Ch[(size_t)r0 * N + c]) =
                    __floats2half2_rn((acc[mt][nt][0] + b0v) * qs, (acc[mt][nt][1] + b1v) * qs);
                *reinterpret_cast<__half2*>(&Ch[(size_t)(r0 + 8) * N + c]) =
                    __floats2half2_rn((acc[mt][nt][2] + b0v) * qs, (acc[mt][nt][3] + b1v) * qs);
            } else {
                float* Cf = (float*)Cout;
                *reinterpret_cast<float2*>(&Cf[(size_t)r0 * N + c]) =
                    make_float2(acc[mt][nt][0] + b0v, acc[mt][nt][1] + b1v);
                *reinterpret_cast<float2*>(&Cf[(size_t)(r0 + 8) * N + c]) =
                    make_float2(acc[mt][nt][2] + b0v, acc[mt][nt][3] + b1v);
            }
        }
    }
}

// ---------------------------------------------------------------------------
// Causal flash attention: 4 warps (32x64 warp tile), K frags via ldmx4,
// V frags via ldmx4.trans straight from [kv][d] rows (no V^T buffer),
// P register-resident, log2-domain softmax (Q pre-scaled by QSCALE),
// 3-stage cp.async KV pipeline with register-rotated bases.
// ---------------------------------------------------------------------------
#define LDS_ 72
#define AT_QBYTES   (128 * LDS_ * 2)
#define AT_KVSTAGE  (2 * 64 * LDS_ * 2)
#define AT_VOFF     (64 * LDS_ * 2)
#define AT_SMEM     (AT_QBYTES + 3 * AT_KVSTAGE)   // 73728 B

__global__ __launch_bounds__(128, 1) void attn_f16_kernel(int T)
{
    extern __shared__ char smraw[];
    const uint32_t sQ  = smem_u32(smraw);
    const uint32_t sKV = sQ + AT_QBYTES;

    const int qt  = gridDim.x - 1 - blockIdx.x;   // heavy tiles first
    const int h   = blockIdx.y;
    const int b   = blockIdx.z;
    const int tid = threadIdx.x;
    const int lane = tid & 31;
    const int warp = tid >> 5;
    const int g = lane >> 2;
    const int t = lane & 3;

    const int q0 = qt * 128;
    const int rb = warp * 32;
    const size_t rowstride = 3 * DIMC;

    // ---- stage Q tile (already scaled by QSCALE)
    __half* Qs = (__half*)smraw;
    #pragma unroll
    for (int it = 0; it < 8; it++) {
        const int idx = it * 128 + tid;
        const int r = idx >> 3, c = idx & 7;
        *reinterpret_cast<uint4*>(&Qs[r * LDS_ + c * 8]) =
            *reinterpret_cast<const uint4*>(
                &g_qkv[(size_t)(b * T + q0 + r) * rowstride + h * HDIM + c * 8]);
    }
    __syncthreads();

    const int f_row = lane & 15, f_k = (lane >> 4) << 3;
    // V trans-frag addressing
    const int v_row = ((lane >> 3) & 1) * 8 + (lane & 7);
    const int v_col = (lane >> 4) * 8;

    unsigned qf[4][2][4];   // [ks][mt]
    #pragma unroll
    for (int ks = 0; ks < 4; ks++)
        #pragma unroll
        for (int mt = 0; mt < 2; mt++)
            ldmx4(qf[ks][mt], sQ + ((rb + mt * 16 + f_row) * LDS_ + ks * 16 + f_k) * 2);

    // hoisted KV staging addresses (K and V rows both from g_qkv)
    const __half* pK = g_qkv + (size_t)(b * T + (tid >> 3)) * rowstride + DIMC + h * HDIM + (tid & 7) * 8;
    const __half* pV = pK + DIMC;
    const uint32_t dKV = ((tid >> 3) * LDS_ + (tid & 7) * 8) * 2;

    auto stageKV = [&](int kv0, uint32_t base) {
        #pragma unroll
        for (int it = 0; it < 4; it++)
            CP_ASYNC16(base + dKV + it * (16 * LDS_ * 2),
                       pK + (size_t)(kv0 + it * 16) * rowstride);
        #pragma unroll
        for (int it = 0; it < 4; it++)
            CP_ASYNC16(base + AT_VOFF + dKV + it * (16 * LDS_ * 2),
                       pV + (size_t)(kv0 + it * 16) * rowstride);
    };

    float o[2][8][4];
    #pragma unroll
    for (int mt = 0; mt < 2; mt++)
        #pragma unroll
        for (int nt = 0; nt < 8; nt++)
            #pragma unroll
            for (int i = 0; i < 4; i++) o[mt][nt][i] = 0.f;

    float mx[2][2], ls[2][2];
    #pragma unroll
    for (int mt = 0; mt < 2; mt++) { mx[mt][0] = mx[mt][1] = -1e30f; ls[mt][0] = ls[mt][1] = 0.f; }

    const uint32_t koff = (f_row * LDS_ + f_k) * 2;

    uint32_t cb0 = sKV, cb1 = sKV + AT_KVSTAGE, cb2 = sKV + 2 * AT_KVSTAGE;

    const int nkv = 2 * qt + 2;
    stageKV(0,  cb0); CP_COMMIT();
    stageKV(64, cb1); CP_COMMIT();

    for (int kt_i = 0; kt_i < nkv; kt_i++) {
        CP_WAIT(1);
        __syncthreads();
        if (kt_i + 2 < nkv) stageKV((kt_i + 2) * 64, cb2);
        CP_COMMIT();

        const uint32_t kb = cb0;
        const uint32_t vb = cb0 + AT_VOFF;
        const int kv0 = kt_i * 64;

        // ---- S = Q @ K^T  (scores already in log2 domain via Q pre-scale)
        float s[2][8][4];
        #pragma unroll
        for (int mt = 0; mt < 2; mt++)
            #pragma unroll
            for (int nt = 0; nt < 8; nt++)
                #pragma unroll
                for (int i = 0; i < 4; i++) s[mt][nt][i] = 0.f;

        #pragma unroll
        for (int ks = 0; ks < 4; ks++) {
            #pragma unroll
            for (int ntp = 0; ntp < 4; ntp++) {
                unsigned kf[4];
                ldmx4(kf, kb + koff + ks * 32 + ntp * (16 * LDS_ * 2));
                #pragma unroll
                for (int mt = 0; mt < 2; mt++) {
                    mma_f16(s[mt][2 * ntp],     qf[ks][mt], kf[0], kf[2]);
                    mma_f16(s[mt][2 * ntp + 1], qf[ks][mt], kf[1], kf[3]);
                }
            }
        }

        // ---- causal mask + log2-domain online softmax
        const bool do_mask = (kt_i >= 2 * qt);
        #pragma unroll
        for (int mt = 0; mt < 2; mt++) {
            const int rg0 = q0 + rb + mt * 16 + g;
            const int rg1 = rg0 + 8;
            float m0loc = -1e30f, m1loc = -1e30f;
            #pragma unroll
            for (int nt = 0; nt < 8; nt++) {
                const int j = kv0 + nt * 8 + 2 * t;
                if (do_mask) {
                    #pragma unroll
                    for (int c = 0; c < 2; c++) {
                        if (j + c > rg0) s[mt][nt][c]     = -1e30f;
                        if (j + c > rg1) s[mt][nt][c + 2] = -1e30f;
                    }
                }
                m0loc = fmaxf(m0loc, fmaxf(s[mt][nt][0], s[mt][nt][1]));
                m1loc = fmaxf(m1loc, fmaxf(s[mt][nt][2], s[mt][nt][3]));
            }
            m0loc = fmaxf(m0loc, __shfl_xor_sync(0xffffffffu, m0loc, 1));
            m0loc = fmaxf(m0loc, __shfl_xor_sync(0xffffffffu, m0loc, 2));
            m1loc = fmaxf(m1loc, __shfl_xor_sync(0xffffffffu, m1loc, 1));
            m1loc = fmaxf(m1loc, __shfl_xor_sync(0xffffffffu, m1loc, 2));

            const float m0n = fmaxf(mx[mt][0], m0loc);
            const float m1n = fmaxf(mx[mt][1], m1loc);
            const float corr0 = ex2f(mx[mt][0] - m0n);
            const float corr1 = ex2f(mx[mt][1] - m1n);

            float l0loc = 0.f, l1loc = 0.f;
            #pragma unroll
            for (int nt = 0; nt < 8; nt++) {
                float p00 = ex2f(s[mt][nt][0] - m0n);
                float p01 = ex2f(s[mt][nt][1] - m0n);
                float p10 = ex2f(s[mt][nt][2] - m1n);
                float p11 = ex2f(s[mt][nt][3] - m1n);
                l0loc += p00 + p01;
                l1loc += p10 + p11;
                s[mt][nt][0] = p00; s[mt][nt][1] = p01;
                s[mt][nt][2] = p10; s[mt][nt][3] = p11;
            }
            l0loc += __shfl_xor_sync(0xffffffffu, l0loc, 1);
            l0loc += __shfl_xor_sync(0xffffffffu, l0loc, 2);
            l1loc += __shfl_xor_sync(0xffffffffu, l1loc, 1);
            l1loc += __shfl_xor_sync(0xffffffffu, l1loc, 2);

            ls[mt][0] = ls[mt][0] * corr0 + l0loc;
            ls[mt][1] = ls[mt][1] * corr1 + l1loc;
            mx[mt][0] = m0n; mx[mt][1] = m1n;

            #pragma unroll
            for (int nt = 0; nt < 8; nt++) {
                o[mt][nt][0] *= corr0; o[mt][nt][1] *= corr0;
                o[mt][nt][2] *= corr1; o[mt][nt][3] *= corr1;
            }
        }

        // ---- O += P @ V   (V B-frags via ldmatrix.trans on [kv][d] rows)
        #pragma unroll
        for (int ks = 0; ks < 4; ks++) {
            unsigned pa[2][4];
            #pragma unroll
            for (int mt = 0; mt < 2; mt++) {
                pa[mt][0] = pack2(s[mt][2 * ks][0],     s[mt][2 * ks][1]);
                pa[mt][1] = pack2(s[mt][2 * ks][2],     s[mt][2 * ks][3]);
                pa[mt][2] = pack2(s[mt][2 * ks + 1][0], s[mt][2 * ks + 1][1]);
                pa[mt][3] = pack2(s[mt][2 * ks + 1][2], s[mt][2 * ks + 1][3]);
            }
            #pragma unroll
            for (int ntp = 0; ntp < 4; ntp++) {
                unsigned vf[4];
                ldmx4t(vf, vb + ((ks * 16 + v_row) * LDS_ + ntp * 16 + v_col) * 2);
                #pragma unroll
                for (int mt = 0; mt < 2; mt++) {
                    mma_f16(o[mt][2 * ntp],     pa[mt], vf[0], vf[1]);
                    mma_f16(o[mt][2 * ntp + 1], pa[mt], vf[2], vf[3]);
                }
            }
        }

        uint32_t t0 = cb0; cb0 = cb1; cb1 = cb2; cb2 = t0;
    }

    // ---- epilogue (fp16 out for proj GEMM)
    #pragma unroll
    for (int mt = 0; mt < 2; mt++) {
        const float inv0 = 1.f / ls[mt][0];
        const float inv1 = 1.f / ls[mt][1];
        const int rg0 = q0 + rb + mt * 16 + g;
        #pragma unroll
        for (int nt = 0; nt < 8; nt++) {
            const int d = nt * 8 + 2 * t;
            *reinterpret_cast<__half2*>(&g_attn[(size_t)(b * T + rg0) * DIMC + h * HDIM + d]) =
                __floats2half2_rn(o[mt][nt][0] * inv0, o[mt][nt][1] * inv0);
            *reinterpret_cast<__half2*>(&g_attn[(size_t)(b * T + rg0 + 8) * DIMC + h * HDIM + d]) =
                __floats2half2_rn(o[mt][nt][2] * inv1, o[mt][nt][3] * inv1);
        }
    }
}

// ---------------------------------------------------------------------------
// Launch
// ---------------------------------------------------------------------------
extern "C" void kernel_launch(void* const* d_in, const int* in_sizes, int n_in,
                              void* d_out, int out_size)
{
    const float* x      = (const float*)d_in[0];
    const float* W_qkv  = (const float*)d_in[1];
    const float* b_qkv  = (const float*)d_in[2];
    const float* W_proj = (const float*)d_in[3];
    const float* b_proj = (const float*)d_in[4];
    float* out = (float*)d_out;

    const int M = in_sizes[0] / DIMC;   // 4096
    const int T = M / BATCH;            // 2048

    __half *xh, *wqkvT, *wprojT, *qkv, *attn;
    cudaGetSymbolAddress((void**)&xh,     g_xh);
    cudaGetSymbolAddress((void**)&wqkvT,  g_wqkvT);
    cudaGetSymbolAddress((void**)&wprojT, g_wprojT);
    cudaGetSymbolAddress((void**)&qkv,    g_qkv);
    cudaGetSymbolAddress((void**)&attn,   g_attn);

    static bool attr_set = false;
    if (!attr_set) {
        cudaFuncSetAttribute(gemm_f16_kernel,
                             cudaFuncAttributeMaxDynamicSharedMemorySize, G_SMEM);
        cudaFuncSetAttribute(attn_f16_kernel,
                             cudaFuncAttributeMaxDynamicSharedMemorySize, AT_SMEM);
        attr_set = true;
    }

    // 0) pre-pass
    conv_f16_kernel<<<(M * DIMC / 4 + 255) / 256, 256>>>(x, xh, M * DIMC / 4);
    transpose_f16_kernel<<<dim3(3 * DIMC / 32, DIMC / 32), dim3(32, 8)>>>(W_qkv, wqkvT, DIMC, 3 * DIMC);
    transpose_f16_kernel<<<dim3(DIMC / 32, DIMC / 32), dim3(32, 8)>>>(W_proj, wprojT, DIMC, DIMC);

    // 1) QKV = x @ W_qkv + b_qkv   (fp16 out, Q columns pre-scaled)
    gemm_f16_kernel<<<dim3(3 * DIMC / 256, M / 128), 256, G_SMEM>>>(
        xh, wqkvT, b_qkv, qkv, M, 3 * DIMC, DIMC, 1, DIMC);

    // 2) causal attention (fp16 out)
    attn_f16_kernel<<<dim3(T / 128, NHEAD, BATCH), 128, AT_SMEM>>>(T);

    // 3) out = attn @ W_proj + b_proj  (fp32 out)
    gemm_f16_kernel<<<dim3(DIMC / 256, M / 128), 256, G_SMEM>>>(
        attn, wprojT, b_proj, out, M, DIMC, DIMC, 0, 0);
}